// round 1
// baseline (speedup 1.0000x reference)
#include <cuda_runtime.h>

#define BATCH 4
#define S_LEN 2048
#define EMB   1024
#define NH    16
#define HD    64
#define M_TOT (BATCH * S_LEN)   // 8192

// Scratch (device globals — no allocation allowed)
__device__ float g_Q[BATCH * NH * S_LEN * HD];     // 32 MB, [B,H,S,D]
__device__ float g_K[BATCH * NH * S_LEN * HD];
__device__ float g_V[BATCH * NH * S_LEN * HD];
__device__ float g_attn[M_TOT * EMB];              // [B,S,E]

// ============================================================================
// SGEMM: C = A[M,K] @ W[N,K]^T + bias[N]
// Tile 128x128x16, 256 threads, 8x8 per thread.
// SCATTER=true: write to [B,H,S,D] layout (m = b*S+s, n = h*D+d)
// ============================================================================
template <bool SCATTER>
__global__ void __launch_bounds__(256)
sgemm_bias(const float* __restrict__ A, const float* __restrict__ W,
           const float* __restrict__ bias, float* __restrict__ C,
           int M, int N, int K)
{
    __shared__ __align__(16) float As[16][132];
    __shared__ __align__(16) float Ws[16][132];

    const int tid = threadIdx.x;
    const int bm  = blockIdx.y;
    const int bn  = blockIdx.x;
    const int tx  = tid & 15;        // 0..15  -> n direction
    const int ty  = tid >> 4;        // 0..15  -> m direction
    const int lrow  = tid >> 2;      // 0..63
    const int lcol4 = (tid & 3) * 4; // {0,4,8,12}

    const float* Ag = A + (size_t)(bm * 128) * K;
    const float* Wg = W + (size_t)(bn * 128) * K;

    float acc[8][8];
#pragma unroll
    for (int i = 0; i < 8; i++)
#pragma unroll
        for (int j = 0; j < 8; j++) acc[i][j] = 0.0f;

    for (int k0 = 0; k0 < K; k0 += 16) {
#pragma unroll
        for (int r = 0; r < 2; r++) {
            int row = lrow + r * 64;
            float4 av = *(const float4*)(Ag + (size_t)row * K + k0 + lcol4);
            As[lcol4 + 0][row] = av.x;
            As[lcol4 + 1][row] = av.y;
            As[lcol4 + 2][row] = av.z;
            As[lcol4 + 3][row] = av.w;
            float4 wv = *(const float4*)(Wg + (size_t)row * K + k0 + lcol4);
            Ws[lcol4 + 0][row] = wv.x;
            Ws[lcol4 + 1][row] = wv.y;
            Ws[lcol4 + 2][row] = wv.z;
            Ws[lcol4 + 3][row] = wv.w;
        }
        __syncthreads();

#pragma unroll
        for (int kk = 0; kk < 16; kk++) {
            float a[8], b[8];
            float4 a0 = *(const float4*)&As[kk][ty * 8];
            float4 a1 = *(const float4*)&As[kk][ty * 8 + 4];
            float4 b0 = *(const float4*)&Ws[kk][tx * 8];
            float4 b1 = *(const float4*)&Ws[kk][tx * 8 + 4];
            a[0] = a0.x; a[1] = a0.y; a[2] = a0.z; a[3] = a0.w;
            a[4] = a1.x; a[5] = a1.y; a[6] = a1.z; a[7] = a1.w;
            b[0] = b0.x; b[1] = b0.y; b[2] = b0.z; b[3] = b0.w;
            b[4] = b1.x; b[5] = b1.y; b[6] = b1.z; b[7] = b1.w;
#pragma unroll
            for (int i = 0; i < 8; i++)
#pragma unroll
                for (int j = 0; j < 8; j++)
                    acc[i][j] = fmaf(a[i], b[j], acc[i][j]);
        }
        __syncthreads();
    }

    const int n0 = bn * 128 + tx * 8;
    float bv[8];
#pragma unroll
    for (int j = 0; j < 8; j++) bv[j] = bias[n0 + j];

#pragma unroll
    for (int i = 0; i < 8; i++) {
        int mrow = bm * 128 + ty * 8 + i;
        float4 v0, v1;
        v0.x = acc[i][0] + bv[0]; v0.y = acc[i][1] + bv[1];
        v0.z = acc[i][2] + bv[2]; v0.w = acc[i][3] + bv[3];
        v1.x = acc[i][4] + bv[4]; v1.y = acc[i][5] + bv[5];
        v1.z = acc[i][6] + bv[6]; v1.w = acc[i][7] + bv[7];
        if (!SCATTER) {
            float* dst = C + (size_t)mrow * N + n0;
            *(float4*)(dst)     = v0;
            *(float4*)(dst + 4) = v1;
        } else {
            // m = b*S + s ; n = h*D + d  ->  out[((b*NH+h)*S + s)*D + d]
            int bb = mrow >> 11;           // /2048
            int ss = mrow & 2047;
            int hh = n0 >> 6;              // /64 (8-wide run never crosses 64)
            int d0 = n0 & 63;
            float* dst = C + (((size_t)(bb * NH + hh) * S_LEN + ss) * HD + d0);
            *(float4*)(dst)     = v0;
            *(float4*)(dst + 4) = v1;
        }
    }
}

// ============================================================================
// Flash attention, fp32. One thread per query row, 128 rows/CTA.
// KV tiles of 32 in shared. q[64], o[64], s[32] in registers.
// grid = (S/128, B*H), block = 128
// ============================================================================
__global__ void __launch_bounds__(128, 1)
flash_attn(const float* __restrict__ Q, const float* __restrict__ K,
           const float* __restrict__ V, float* __restrict__ Out)
{
    __shared__ __align__(16) float4 ks[32][16];   // 8 KB
    __shared__ __align__(16) float4 vs[32][16];   // 8 KB

    const int bh  = blockIdx.y;
    const int b   = bh >> 4;
    const int h   = bh & 15;
    const int row = blockIdx.x * 128 + threadIdx.x;   // query index in S

    const float* Qb = Q + (size_t)bh * S_LEN * HD;
    const float* Kb = K + (size_t)bh * S_LEN * HD;
    const float* Vb = V + (size_t)bh * S_LEN * HD;

    float q[64], o[64];
#pragma unroll
    for (int d4 = 0; d4 < 16; d4++) {
        float4 t = *(const float4*)(Qb + (size_t)row * HD + d4 * 4);
        q[4 * d4 + 0] = t.x; q[4 * d4 + 1] = t.y;
        q[4 * d4 + 2] = t.z; q[4 * d4 + 3] = t.w;
    }
#pragma unroll
    for (int d = 0; d < 64; d++) o[d] = 0.0f;

    float m = -1e30f, l = 0.0f;

    for (int kt = 0; kt < S_LEN / 32; kt++) {
        // cooperative tile load: 512 float4 each, 4 per thread
        const float4* Kg = (const float4*)(Kb + (size_t)kt * 32 * HD);
        const float4* Vg = (const float4*)(Vb + (size_t)kt * 32 * HD);
#pragma unroll
        for (int r = 0; r < 4; r++) {
            int f = threadIdx.x + r * 128;
            ((float4*)ks)[f] = Kg[f];
            ((float4*)vs)[f] = Vg[f];
        }
        __syncthreads();

        // scores: s[j] = q . k_j   (32 independent FFMA chains; LDS broadcast)
        float s[32];
#pragma unroll
        for (int j = 0; j < 32; j++) s[j] = 0.0f;
#pragma unroll
        for (int d4 = 0; d4 < 16; d4++) {
            float q0 = q[4 * d4 + 0], q1 = q[4 * d4 + 1];
            float q2 = q[4 * d4 + 2], q3 = q[4 * d4 + 3];
#pragma unroll
            for (int j = 0; j < 32; j++) {
                float4 kv = ks[j][d4];
                s[j] = fmaf(q0, kv.x, s[j]);
                s[j] = fmaf(q1, kv.y, s[j]);
                s[j] = fmaf(q2, kv.z, s[j]);
                s[j] = fmaf(q3, kv.w, s[j]);
            }
        }

        // online softmax (scale 1/sqrt(64) = 0.125)
        float mt = m;
#pragma unroll
        for (int j = 0; j < 32; j++) {
            s[j] *= 0.125f;
            mt = fmaxf(mt, s[j]);
        }
        float corr = __expf(m - mt);
        m = mt;
        float psum = 0.0f;
#pragma unroll
        for (int j = 0; j < 32; j++) {
            s[j] = __expf(s[j] - mt);
            psum += s[j];
        }
        l = l * corr + psum;
#pragma unroll
        for (int d = 0; d < 64; d++) o[d] *= corr;

        // o += P @ V  (j outer: 64 independent accumulators)
#pragma unroll
        for (int j = 0; j < 32; j++) {
            float p = s[j];
#pragma unroll
            for (int d4 = 0; d4 < 16; d4++) {
                float4 vv = vs[j][d4];
                o[4 * d4 + 0] = fmaf(p, vv.x, o[4 * d4 + 0]);
                o[4 * d4 + 1] = fmaf(p, vv.y, o[4 * d4 + 1]);
                o[4 * d4 + 2] = fmaf(p, vv.z, o[4 * d4 + 2]);
                o[4 * d4 + 3] = fmaf(p, vv.w, o[4 * d4 + 3]);
            }
        }
        __syncthreads();
    }

    // write to [B,S,E] for final projection
    float inv = 1.0f / l;
    float* outp = Out + ((size_t)(b * S_LEN + row)) * EMB + h * HD;
#pragma unroll
    for (int d4 = 0; d4 < 16; d4++) {
        float4 t;
        t.x = o[4 * d4 + 0] * inv; t.y = o[4 * d4 + 1] * inv;
        t.z = o[4 * d4 + 2] * inv; t.w = o[4 * d4 + 3] * inv;
        *(float4*)(outp + d4 * 4) = t;
    }
}

// ============================================================================
// Launch
// ============================================================================
extern "C" void kernel_launch(void* const* d_in, const int* in_sizes, int n_in,
                              void* d_out, int out_size)
{
    const float* x  = (const float*)d_in[0];
    const float* Wq = (const float*)d_in[1];
    const float* bq = (const float*)d_in[2];
    const float* Wk = (const float*)d_in[3];
    const float* bk = (const float*)d_in[4];
    const float* Wv = (const float*)d_in[5];
    const float* bv = (const float*)d_in[6];
    const float* Wo = (const float*)d_in[7];
    const float* bo = (const float*)d_in[8];
    float* out = (float*)d_out;

    float *Qp, *Kp, *Vp, *Ap;
    cudaGetSymbolAddress((void**)&Qp, g_Q);
    cudaGetSymbolAddress((void**)&Kp, g_K);
    cudaGetSymbolAddress((void**)&Vp, g_V);
    cudaGetSymbolAddress((void**)&Ap, g_attn);

    dim3 gg(EMB / 128, M_TOT / 128);   // (8, 64)
    dim3 gb(256);

    sgemm_bias<true><<<gg, gb>>>(x, Wq, bq, Qp, M_TOT, EMB, EMB);
    sgemm_bias<true><<<gg, gb>>>(x, Wk, bk, Kp, M_TOT, EMB, EMB);
    sgemm_bias<true><<<gg, gb>>>(x, Wv, bv, Vp, M_TOT, EMB, EMB);

    dim3 ga(S_LEN / 128, BATCH * NH);  // (16, 64)
    flash_attn<<<ga, 128>>>(Qp, Kp, Vp, Ap);

    sgemm_bias<false><<<gg, gb>>>(Ap, Wo, bo, out, M_TOT, EMB, EMB);
}

// round 3
// speedup vs baseline: 1.3860x; 1.3860x over previous
#include <cuda_runtime.h>
#include <cuda_bf16.h>
#include <cstdint>

#define BATCH 4
#define S_LEN 2048
#define EMB   1024
#define NH    16
#define HD    64
#define M_TOT (BATCH * S_LEN)   // 8192

// ---------------------------------------------------------------------------
// Scratch (device globals — no allocation allowed)
// ---------------------------------------------------------------------------
__device__ float g_Q[(size_t)BATCH * NH * S_LEN * HD];
__device__ float g_K[(size_t)BATCH * NH * S_LEN * HD];
__device__ float g_V[(size_t)BATCH * NH * S_LEN * HD];
__device__ float g_attn[(size_t)M_TOT * EMB];

__device__ __nv_bfloat16 g_xhi[(size_t)M_TOT * EMB];
__device__ __nv_bfloat16 g_xlo[(size_t)M_TOT * EMB];
__device__ __nv_bfloat16 g_whi[4][(size_t)EMB * EMB];
__device__ __nv_bfloat16 g_wlo[4][(size_t)EMB * EMB];
__device__ __nv_bfloat16 g_ahi[(size_t)M_TOT * EMB];
__device__ __nv_bfloat16 g_alo[(size_t)M_TOT * EMB];

// ---------------------------------------------------------------------------
// helpers
// ---------------------------------------------------------------------------
__device__ __forceinline__ uint32_t smem_u32(const void* p) {
    uint32_t a;
    asm("{ .reg .u64 t; cvta.to.shared.u64 t, %1; cvt.u32.u64 %0, t; }"
        : "=r"(a) : "l"(p));
    return a;
}

__device__ __forceinline__ void cp_async16(uint32_t dst, const void* src) {
    asm volatile("cp.async.cg.shared.global [%0], [%1], 16;"
                 :: "r"(dst), "l"(__cvta_generic_to_global(src)) : "memory");
}
#define CP_COMMIT()  asm volatile("cp.async.commit_group;" ::: "memory")
#define CP_WAIT(n)   asm volatile("cp.async.wait_group %0;" :: "n"(n) : "memory")

__device__ __forceinline__ void ldm_x4(uint32_t* r, uint32_t addr) {
    asm volatile("ldmatrix.sync.aligned.m8n8.x4.shared.b16 {%0,%1,%2,%3}, [%4];"
                 : "=r"(r[0]), "=r"(r[1]), "=r"(r[2]), "=r"(r[3]) : "r"(addr));
}
__device__ __forceinline__ void ldm_x2(uint32_t* r, uint32_t addr) {
    asm volatile("ldmatrix.sync.aligned.m8n8.x2.shared.b16 {%0,%1}, [%2];"
                 : "=r"(r[0]), "=r"(r[1]) : "r"(addr));
}
__device__ __forceinline__ void mma_bf16(float* c, const uint32_t* a, const uint32_t* b) {
    asm volatile(
        "mma.sync.aligned.m16n8k16.row.col.f32.bf16.bf16.f32 "
        "{%0,%1,%2,%3}, {%4,%5,%6,%7}, {%8,%9}, {%0,%1,%2,%3};"
        : "+f"(c[0]), "+f"(c[1]), "+f"(c[2]), "+f"(c[3])
        : "r"(a[0]), "r"(a[1]), "r"(a[2]), "r"(a[3]), "r"(b[0]), "r"(b[1]));
}

// ---------------------------------------------------------------------------
// fp32 -> bf16 hi/lo split (memory-bound)
// ---------------------------------------------------------------------------
__global__ void __launch_bounds__(256)
convert_split(const float4* __restrict__ in, __nv_bfloat162* __restrict__ hi,
              __nv_bfloat162* __restrict__ lo, int n4)
{
    int i = blockIdx.x * 256 + threadIdx.x;
    if (i >= n4) return;
    float4 v = in[i];
    __nv_bfloat16 h0 = __float2bfloat16(v.x);
    __nv_bfloat16 h1 = __float2bfloat16(v.y);
    __nv_bfloat16 h2 = __float2bfloat16(v.z);
    __nv_bfloat16 h3 = __float2bfloat16(v.w);
    __nv_bfloat16 l0 = __float2bfloat16(v.x - __bfloat162float(h0));
    __nv_bfloat16 l1 = __float2bfloat16(v.y - __bfloat162float(h1));
    __nv_bfloat16 l2 = __float2bfloat16(v.z - __bfloat162float(h2));
    __nv_bfloat16 l3 = __float2bfloat16(v.w - __bfloat162float(h3));
    hi[2 * i + 0] = __halves2bfloat162(h0, h1);
    hi[2 * i + 1] = __halves2bfloat162(h2, h3);
    lo[2 * i + 0] = __halves2bfloat162(l0, l1);
    lo[2 * i + 1] = __halves2bfloat162(l2, l3);
}

// ---------------------------------------------------------------------------
// warp-MMA split-bf16 GEMM: C[M,N] = A[M,K] @ B[N,K]^T + bias
//   CTA tile 128x128, 8 warps (2m x 4n), warp tile 64x32, BK=32,
//   double-buffered cp.async, padded smem rows (80B) for conflict-free ldmatrix.
//   3 split terms: Ah*Bh + Ah*Bl + Al*Bh  (fp32 accum in registers)
//   SCATTER=true: write [B,H,S,D] layout
// ---------------------------------------------------------------------------
#define ROWB 80                       // smem row stride in bytes (32 bf16 + pad)
#define TILE_B (128 * ROWB)           // 10240 B per tile
#define ST_AH 0
#define ST_AL (1 * TILE_B)
#define ST_BH (2 * TILE_B)
#define ST_BL (3 * TILE_B)
#define STAGE_B (4 * TILE_B)          // 40960 B per stage
#define GEMM_SMEM (2 * STAGE_B)       // 81920 B

template <bool SCATTER>
__global__ void __launch_bounds__(256)
gemm_mma(const __nv_bfloat16* __restrict__ Ahi, const __nv_bfloat16* __restrict__ Alo,
         const __nv_bfloat16* __restrict__ Bhi, const __nv_bfloat16* __restrict__ Blo,
         const float* __restrict__ bias, float* __restrict__ C)
{
    extern __shared__ char smem[];
    const uint32_t sb = smem_u32(smem);
    const int tid = threadIdx.x;
    const int wid = tid >> 5;
    const int lid = tid & 31;
    const int tm  = blockIdx.y * 128;
    const int tn  = blockIdx.x * 128;
    const int wm  = wid >> 2;          // 0..1
    const int wn  = wid & 3;           // 0..3

    // staging coordinates: 2 uint4 per thread per tile
    const int r0 = tid >> 2;           // 0..63  (row within tile, +64 for t=1)
    const int c16 = (tid & 3) * 16;    // byte col within 64B row

    const __nv_bfloat16* gA[2] = { Ahi + (size_t)tm * EMB, Alo + (size_t)tm * EMB };
    const __nv_bfloat16* gB[2] = { Bhi + (size_t)tn * EMB, Blo + (size_t)tn * EMB };

    auto stage = [&](int buf, int kc) {
        const uint32_t base = sb + buf * STAGE_B;
        const int gcol = kc * 32 + (c16 >> 1);       // bf16 col
#pragma unroll
        for (int t = 0; t < 2; t++) {
            int row = r0 + t * 64;
            uint32_t so = row * ROWB + c16;
            cp_async16(base + ST_AH + so, gA[0] + (size_t)row * EMB + gcol);
            cp_async16(base + ST_AL + so, gA[1] + (size_t)row * EMB + gcol);
            cp_async16(base + ST_BH + so, gB[0] + (size_t)row * EMB + gcol);
            cp_async16(base + ST_BL + so, gB[1] + (size_t)row * EMB + gcol);
        }
        CP_COMMIT();
    };

    float acc[4][4][4];
#pragma unroll
    for (int i = 0; i < 4; i++)
#pragma unroll
        for (int j = 0; j < 4; j++)
#pragma unroll
            for (int k = 0; k < 4; k++) acc[i][j][k] = 0.0f;

    // ldmatrix lane address components
    const int a_row = wm * 64 + (lid & 15);          // + mi*16
    const int a_kh  = (lid >> 4) * 16;               // byte offset of k-half
    const int b_row = wn * 32 + (lid & 7);           // + ni*8
    const int b_kh  = ((lid >> 3) & 1) * 16;

    stage(0, 0);

#pragma unroll 1
    for (int kc = 0; kc < EMB / 32; kc++) {
        if (kc + 1 < EMB / 32) { stage((kc + 1) & 1, kc + 1); CP_WAIT(1); }
        else                   { CP_WAIT(0); }
        __syncthreads();

        const uint32_t bufb = sb + (kc & 1) * STAGE_B;
#pragma unroll
        for (int ks = 0; ks < 2; ks++) {
            const uint32_t kso = ks * 32;
            uint32_t ah[4][4], al[4][4], bh[4][2], bl[4][2];
#pragma unroll
            for (int mi = 0; mi < 4; mi++) {
                uint32_t ra = (a_row + mi * 16) * ROWB + kso + a_kh;
                ldm_x4(ah[mi], bufb + ST_AH + ra);
                ldm_x4(al[mi], bufb + ST_AL + ra);
            }
#pragma unroll
            for (int ni = 0; ni < 4; ni++) {
                uint32_t rb = (b_row + ni * 8) * ROWB + kso + b_kh;
                ldm_x2(bh[ni], bufb + ST_BH + rb);
                ldm_x2(bl[ni], bufb + ST_BL + rb);
            }
#pragma unroll
            for (int mi = 0; mi < 4; mi++)
#pragma unroll
                for (int ni = 0; ni < 4; ni++) {
                    mma_bf16(acc[mi][ni], ah[mi], bh[ni]);
                    mma_bf16(acc[mi][ni], ah[mi], bl[ni]);
                    mma_bf16(acc[mi][ni], al[mi], bh[ni]);
                }
        }
        __syncthreads();
    }

    // epilogue: direct stores (+bias, +scatter)
    const int g   = lid >> 2;          // groupID
    const int tig = lid & 3;
#pragma unroll
    for (int ni = 0; ni < 4; ni++) {
        const int n = tn + wn * 32 + ni * 8 + tig * 2;
        const float b0 = bias[n], b1 = bias[n + 1];
#pragma unroll
        for (int mi = 0; mi < 4; mi++) {
#pragma unroll
            for (int half = 0; half < 2; half++) {
                int m = tm + wm * 64 + mi * 16 + g + half * 8;
                float2 v;
                v.x = acc[mi][ni][half * 2 + 0] + b0;
                v.y = acc[mi][ni][half * 2 + 1] + b1;
                if (!SCATTER) {
                    *(float2*)(C + (size_t)m * EMB + n) = v;
                } else {
                    int bb = m >> 11, ss = m & 2047;
                    int hh = n >> 6,  dd = n & 63;
                    *(float2*)(C + (((size_t)(bb * NH + hh) * S_LEN) + ss) * HD + dd) = v;
                }
            }
        }
    }
}

// ---------------------------------------------------------------------------
// Flash attention, fp32 (unchanged — passes at rel_err 1.3e-6)
// ---------------------------------------------------------------------------
__global__ void __launch_bounds__(128, 1)
flash_attn(const float* __restrict__ Q, const float* __restrict__ K,
           const float* __restrict__ V, float* __restrict__ Out)
{
    __shared__ __align__(16) float4 ks[32][16];
    __shared__ __align__(16) float4 vs[32][16];

    const int bh  = blockIdx.y;
    const int b   = bh >> 4;
    const int h   = bh & 15;
    const int row = blockIdx.x * 128 + threadIdx.x;

    const float* Qb = Q + (size_t)bh * S_LEN * HD;
    const float* Kb = K + (size_t)bh * S_LEN * HD;
    const float* Vb = V + (size_t)bh * S_LEN * HD;

    float q[64], o[64];
#pragma unroll
    for (int d4 = 0; d4 < 16; d4++) {
        float4 t = *(const float4*)(Qb + (size_t)row * HD + d4 * 4);
        q[4 * d4 + 0] = t.x; q[4 * d4 + 1] = t.y;
        q[4 * d4 + 2] = t.z; q[4 * d4 + 3] = t.w;
    }
#pragma unroll
    for (int d = 0; d < 64; d++) o[d] = 0.0f;

    float m = -1e30f, l = 0.0f;

    for (int kt = 0; kt < S_LEN / 32; kt++) {
        const float4* Kg = (const float4*)(Kb + (size_t)kt * 32 * HD);
        const float4* Vg = (const float4*)(Vb + (size_t)kt * 32 * HD);
#pragma unroll
        for (int r = 0; r < 4; r++) {
            int f = threadIdx.x + r * 128;
            ((float4*)ks)[f] = Kg[f];
            ((float4*)vs)[f] = Vg[f];
        }
        __syncthreads();

        float s[32];
#pragma unroll
        for (int j = 0; j < 32; j++) s[j] = 0.0f;
#pragma unroll
        for (int d4 = 0; d4 < 16; d4++) {
            float q0 = q[4 * d4 + 0], q1 = q[4 * d4 + 1];
            float q2 = q[4 * d4 + 2], q3 = q[4 * d4 + 3];
#pragma unroll
            for (int j = 0; j < 32; j++) {
                float4 kv = ks[j][d4];
                s[j] = fmaf(q0, kv.x, s[j]);
                s[j] = fmaf(q1, kv.y, s[j]);
                s[j] = fmaf(q2, kv.z, s[j]);
                s[j] = fmaf(q3, kv.w, s[j]);
            }
        }

        float mt = m;
#pragma unroll
        for (int j = 0; j < 32; j++) {
            s[j] *= 0.125f;
            mt = fmaxf(mt, s[j]);
        }
        float corr = __expf(m - mt);
        m = mt;
        float psum = 0.0f;
#pragma unroll
        for (int j = 0; j < 32; j++) {
            s[j] = __expf(s[j] - mt);
            psum += s[j];
        }
        l = l * corr + psum;
#pragma unroll
        for (int d = 0; d < 64; d++) o[d] *= corr;

#pragma unroll
        for (int j = 0; j < 32; j++) {
            float p = s[j];
#pragma unroll
            for (int d4 = 0; d4 < 16; d4++) {
                float4 vv = vs[j][d4];
                o[4 * d4 + 0] = fmaf(p, vv.x, o[4 * d4 + 0]);
                o[4 * d4 + 1] = fmaf(p, vv.y, o[4 * d4 + 1]);
                o[4 * d4 + 2] = fmaf(p, vv.z, o[4 * d4 + 2]);
                o[4 * d4 + 3] = fmaf(p, vv.w, o[4 * d4 + 3]);
            }
        }
        __syncthreads();
    }

    float inv = 1.0f / l;
    float* outp = Out + ((size_t)(b * S_LEN + row)) * EMB + h * HD;
#pragma unroll
    for (int d4 = 0; d4 < 16; d4++) {
        float4 t;
        t.x = o[4 * d4 + 0] * inv; t.y = o[4 * d4 + 1] * inv;
        t.z = o[4 * d4 + 2] * inv; t.w = o[4 * d4 + 3] * inv;
        *(float4*)(outp + d4 * 4) = t;
    }
}

// ---------------------------------------------------------------------------
// Launch
// ---------------------------------------------------------------------------
extern "C" void kernel_launch(void* const* d_in, const int* in_sizes, int n_in,
                              void* d_out, int out_size)
{
    const float* x  = (const float*)d_in[0];
    const float* Wq = (const float*)d_in[1];
    const float* bq = (const float*)d_in[2];
    const float* Wk = (const float*)d_in[3];
    const float* bk = (const float*)d_in[4];
    const float* Wv = (const float*)d_in[5];
    const float* bv = (const float*)d_in[6];
    const float* Wo = (const float*)d_in[7];
    const float* bo = (const float*)d_in[8];
    float* out = (float*)d_out;

    float *Qp, *Kp, *Vp, *Ap;
    __nv_bfloat16 *xhi, *xlo, *whi, *wlo, *ahi, *alo;
    cudaGetSymbolAddress((void**)&Qp,  g_Q);
    cudaGetSymbolAddress((void**)&Kp,  g_K);
    cudaGetSymbolAddress((void**)&Vp,  g_V);
    cudaGetSymbolAddress((void**)&Ap,  g_attn);
    cudaGetSymbolAddress((void**)&xhi, g_xhi);
    cudaGetSymbolAddress((void**)&xlo, g_xlo);
    cudaGetSymbolAddress((void**)&whi, g_whi);
    cudaGetSymbolAddress((void**)&wlo, g_wlo);
    cudaGetSymbolAddress((void**)&ahi, g_ahi);
    cudaGetSymbolAddress((void**)&alo, g_alo);

    cudaFuncSetAttribute(gemm_mma<true>,  cudaFuncAttributeMaxDynamicSharedMemorySize, GEMM_SMEM);
    cudaFuncSetAttribute(gemm_mma<false>, cudaFuncAttributeMaxDynamicSharedMemorySize, GEMM_SMEM);

    const int XN4 = M_TOT * EMB / 4;
    const int WN4 = EMB * EMB / 4;
    const size_t WSZ = (size_t)EMB * EMB;

    convert_split<<<(XN4 + 255) / 256, 256>>>((const float4*)x,
        (__nv_bfloat162*)xhi, (__nv_bfloat162*)xlo, XN4);
    convert_split<<<(WN4 + 255) / 256, 256>>>((const float4*)Wq,
        (__nv_bfloat162*)(whi + 0 * WSZ), (__nv_bfloat162*)(wlo + 0 * WSZ), WN4);
    convert_split<<<(WN4 + 255) / 256, 256>>>((const float4*)Wk,
        (__nv_bfloat162*)(whi + 1 * WSZ), (__nv_bfloat162*)(wlo + 1 * WSZ), WN4);
    convert_split<<<(WN4 + 255) / 256, 256>>>((const float4*)Wv,
        (__nv_bfloat162*)(whi + 2 * WSZ), (__nv_bfloat162*)(wlo + 2 * WSZ), WN4);
    convert_split<<<(WN4 + 255) / 256, 256>>>((const float4*)Wo,
        (__nv_bfloat162*)(whi + 3 * WSZ), (__nv_bfloat162*)(wlo + 3 * WSZ), WN4);

    dim3 gg(EMB / 128, M_TOT / 128);   // (8, 64)
    gemm_mma<true><<<gg, 256, GEMM_SMEM>>>(xhi, xlo, whi + 0 * WSZ, wlo + 0 * WSZ, bq, Qp);
    gemm_mma<true><<<gg, 256, GEMM_SMEM>>>(xhi, xlo, whi + 1 * WSZ, wlo + 1 * WSZ, bk, Kp);
    gemm_mma<true><<<gg, 256, GEMM_SMEM>>>(xhi, xlo, whi + 2 * WSZ, wlo + 2 * WSZ, bv, Vp);

    dim3 ga(S_LEN / 128, BATCH * NH);  // (16, 64)
    flash_attn<<<ga, 128>>>(Qp, Kp, Vp, Ap);

    convert_split<<<(XN4 + 255) / 256, 256>>>((const float4*)Ap,
        (__nv_bfloat162*)ahi, (__nv_bfloat162*)alo, XN4);
    gemm_mma<false><<<gg, 256, GEMM_SMEM>>>(ahi, alo, whi + 3 * WSZ, wlo + 3 * WSZ, bo, out);
}

// round 5
// speedup vs baseline: 3.1218x; 2.2524x over previous
#include <cuda_runtime.h>
#include <cuda_bf16.h>
#include <cstdint>

#define BATCH 4
#define S_LEN 2048
#define EMB   1024
#define NH    16
#define HD    64
#define M_TOT (BATCH * S_LEN)   // 8192
#define BH    (BATCH * NH)      // 64

// ---------------------------------------------------------------------------
// Scratch (device globals — no allocation allowed)
// ---------------------------------------------------------------------------
__device__ __nv_bfloat16 g_xhi[(size_t)M_TOT * EMB];
__device__ __nv_bfloat16 g_xlo[(size_t)M_TOT * EMB];
__device__ __nv_bfloat16 g_whi[4][(size_t)EMB * EMB];
__device__ __nv_bfloat16 g_wlo[4][(size_t)EMB * EMB];
__device__ __nv_bfloat16 g_qhi[(size_t)BH * S_LEN * HD];
__device__ __nv_bfloat16 g_qlo[(size_t)BH * S_LEN * HD];
__device__ __nv_bfloat16 g_khi[(size_t)BH * S_LEN * HD];
__device__ __nv_bfloat16 g_klo[(size_t)BH * S_LEN * HD];
__device__ __nv_bfloat16 g_vhi[(size_t)BH * S_LEN * HD];
__device__ __nv_bfloat16 g_vlo[(size_t)BH * S_LEN * HD];
__device__ __nv_bfloat16 g_ahi[(size_t)M_TOT * EMB];
__device__ __nv_bfloat16 g_alo[(size_t)M_TOT * EMB];

// ---------------------------------------------------------------------------
// helpers
// ---------------------------------------------------------------------------
__device__ __forceinline__ uint32_t smem_u32(const void* p) {
    uint32_t a;
    asm("{ .reg .u64 t; cvta.to.shared.u64 t, %1; cvt.u32.u64 %0, t; }"
        : "=r"(a) : "l"(p));
    return a;
}
__device__ __forceinline__ void cp_async16(uint32_t dst, const void* src) {
    asm volatile("cp.async.cg.shared.global [%0], [%1], 16;"
                 :: "r"(dst), "l"(__cvta_generic_to_global(src)) : "memory");
}
#define CP_COMMIT()  asm volatile("cp.async.commit_group;" ::: "memory")
#define CP_WAIT(n)   asm volatile("cp.async.wait_group %0;" :: "n"(n) : "memory")

__device__ __forceinline__ void ldm_x4(uint32_t* r, uint32_t addr) {
    asm volatile("ldmatrix.sync.aligned.m8n8.x4.shared.b16 {%0,%1,%2,%3}, [%4];"
                 : "=r"(r[0]), "=r"(r[1]), "=r"(r[2]), "=r"(r[3]) : "r"(addr));
}
__device__ __forceinline__ void ldm_x2(uint32_t* r, uint32_t addr) {
    asm volatile("ldmatrix.sync.aligned.m8n8.x2.shared.b16 {%0,%1}, [%2];"
                 : "=r"(r[0]), "=r"(r[1]) : "r"(addr));
}
__device__ __forceinline__ void ldm_x2_t(uint32_t* r, uint32_t addr) {
    asm volatile("ldmatrix.sync.aligned.m8n8.x2.trans.shared.b16 {%0,%1}, [%2];"
                 : "=r"(r[0]), "=r"(r[1]) : "r"(addr));
}
__device__ __forceinline__ void mma_bf16(float* c, const uint32_t* a, const uint32_t* b) {
    asm volatile(
        "mma.sync.aligned.m16n8k16.row.col.f32.bf16.bf16.f32 "
        "{%0,%1,%2,%3}, {%4,%5,%6,%7}, {%8,%9}, {%0,%1,%2,%3};"
        : "+f"(c[0]), "+f"(c[1]), "+f"(c[2]), "+f"(c[3])
        : "r"(a[0]), "r"(a[1]), "r"(a[2]), "r"(a[3]), "r"(b[0]), "r"(b[1]));
}
// pack two fp32 -> bf16x2 register (lo in low half, hi in high half), RN rounding
__device__ __forceinline__ uint32_t pack_bf16x2(float lo, float hi) {
    uint32_t r;
    asm("cvt.rn.bf16x2.f32 %0, %1, %2;" : "=r"(r) : "f"(hi), "f"(lo));
    return r;
}

// ---------------------------------------------------------------------------
// fp32 -> bf16 hi/lo split (memory-bound)
// ---------------------------------------------------------------------------
__global__ void __launch_bounds__(256)
convert_split(const float4* __restrict__ in, __nv_bfloat162* __restrict__ hi,
              __nv_bfloat162* __restrict__ lo, int n4)
{
    int i = blockIdx.x * 256 + threadIdx.x;
    if (i >= n4) return;
    float4 v = in[i];
    __nv_bfloat16 h0 = __float2bfloat16(v.x);
    __nv_bfloat16 h1 = __float2bfloat16(v.y);
    __nv_bfloat16 h2 = __float2bfloat16(v.z);
    __nv_bfloat16 h3 = __float2bfloat16(v.w);
    __nv_bfloat16 l0 = __float2bfloat16(v.x - __bfloat162float(h0));
    __nv_bfloat16 l1 = __float2bfloat16(v.y - __bfloat162float(h1));
    __nv_bfloat16 l2 = __float2bfloat16(v.z - __bfloat162float(h2));
    __nv_bfloat16 l3 = __float2bfloat16(v.w - __bfloat162float(h3));
    hi[2 * i + 0] = __halves2bfloat162(h0, h1);
    hi[2 * i + 1] = __halves2bfloat162(h2, h3);
    lo[2 * i + 0] = __halves2bfloat162(l0, l1);
    lo[2 * i + 1] = __halves2bfloat162(l2, l3);
}

// ---------------------------------------------------------------------------
// warp-MMA split-bf16 GEMM: C[M,N] = A[M,K] @ B[N,K]^T + bias
//   MODE 0: fp32 C, row-major [M,N]
//   MODE 1: split bf16 hi/lo, scattered to [B,H,S,D]
// ---------------------------------------------------------------------------
#define ROWB 80
#define TILE_B (128 * ROWB)
#define ST_AH 0
#define ST_AL (1 * TILE_B)
#define ST_BH (2 * TILE_B)
#define ST_BL (3 * TILE_B)
#define STAGE_B (4 * TILE_B)
#define GEMM_SMEM (2 * STAGE_B)

template <int MODE>
__global__ void __launch_bounds__(256)
gemm_mma(const __nv_bfloat16* __restrict__ Ahi, const __nv_bfloat16* __restrict__ Alo,
         const __nv_bfloat16* __restrict__ Bhi, const __nv_bfloat16* __restrict__ Blo,
         const float* __restrict__ bias, float* __restrict__ C,
         __nv_bfloat16* __restrict__ Chi, __nv_bfloat16* __restrict__ Clo)
{
    extern __shared__ char smem[];
    const uint32_t sb = smem_u32(smem);
    const int tid = threadIdx.x;
    const int wid = tid >> 5;
    const int lid = tid & 31;
    const int tm  = blockIdx.y * 128;
    const int tn  = blockIdx.x * 128;
    const int wm  = wid >> 2;
    const int wn  = wid & 3;

    const int r0 = tid >> 2;
    const int c16 = (tid & 3) * 16;

    const __nv_bfloat16* gA[2] = { Ahi + (size_t)tm * EMB, Alo + (size_t)tm * EMB };
    const __nv_bfloat16* gB[2] = { Bhi + (size_t)tn * EMB, Blo + (size_t)tn * EMB };

    auto stage = [&](int buf, int kc) {
        const uint32_t base = sb + buf * STAGE_B;
        const int gcol = kc * 32 + (c16 >> 1);
#pragma unroll
        for (int t = 0; t < 2; t++) {
            int row = r0 + t * 64;
            uint32_t so = row * ROWB + c16;
            cp_async16(base + ST_AH + so, gA[0] + (size_t)row * EMB + gcol);
            cp_async16(base + ST_AL + so, gA[1] + (size_t)row * EMB + gcol);
            cp_async16(base + ST_BH + so, gB[0] + (size_t)row * EMB + gcol);
            cp_async16(base + ST_BL + so, gB[1] + (size_t)row * EMB + gcol);
        }
        CP_COMMIT();
    };

    float acc[4][4][4];
#pragma unroll
    for (int i = 0; i < 4; i++)
#pragma unroll
        for (int j = 0; j < 4; j++)
#pragma unroll
            for (int k = 0; k < 4; k++) acc[i][j][k] = 0.0f;

    const int a_row = wm * 64 + (lid & 15);
    const int a_kh  = (lid >> 4) * 16;
    const int b_row = wn * 32 + (lid & 7);
    const int b_kh  = ((lid >> 3) & 1) * 16;

    stage(0, 0);

#pragma unroll 1
    for (int kc = 0; kc < EMB / 32; kc++) {
        if (kc + 1 < EMB / 32) { stage((kc + 1) & 1, kc + 1); CP_WAIT(1); }
        else                   { CP_WAIT(0); }
        __syncthreads();

        const uint32_t bufb = sb + (kc & 1) * STAGE_B;
#pragma unroll
        for (int ks = 0; ks < 2; ks++) {
            const uint32_t kso = ks * 32;
            uint32_t ah[4][4], al[4][4], bh[4][2], bl[4][2];
#pragma unroll
            for (int mi = 0; mi < 4; mi++) {
                uint32_t ra = (a_row + mi * 16) * ROWB + kso + a_kh;
                ldm_x4(ah[mi], bufb + ST_AH + ra);
                ldm_x4(al[mi], bufb + ST_AL + ra);
            }
#pragma unroll
            for (int ni = 0; ni < 4; ni++) {
                uint32_t rb = (b_row + ni * 8) * ROWB + kso + b_kh;
                ldm_x2(bh[ni], bufb + ST_BH + rb);
                ldm_x2(bl[ni], bufb + ST_BL + rb);
            }
#pragma unroll
            for (int mi = 0; mi < 4; mi++)
#pragma unroll
                for (int ni = 0; ni < 4; ni++) {
                    mma_bf16(acc[mi][ni], ah[mi], bh[ni]);
                    mma_bf16(acc[mi][ni], ah[mi], bl[ni]);
                    mma_bf16(acc[mi][ni], al[mi], bh[ni]);
                }
        }
        __syncthreads();
    }

    const int g   = lid >> 2;
    const int tig = lid & 3;
#pragma unroll
    for (int ni = 0; ni < 4; ni++) {
        const int n = tn + wn * 32 + ni * 8 + tig * 2;
        const float b0 = bias[n], b1 = bias[n + 1];
#pragma unroll
        for (int mi = 0; mi < 4; mi++) {
#pragma unroll
            for (int half = 0; half < 2; half++) {
                int m = tm + wm * 64 + mi * 16 + g + half * 8;
                float vx = acc[mi][ni][half * 2 + 0] + b0;
                float vy = acc[mi][ni][half * 2 + 1] + b1;
                if (MODE == 0) {
                    float2 v = {vx, vy};
                    *(float2*)(C + (size_t)m * EMB + n) = v;
                } else {
                    int bb = m >> 11, ss = m & 2047;
                    int hh = n >> 6,  dd = n & 63;
                    size_t idx = (((size_t)(bb * NH + hh) * S_LEN) + ss) * HD + dd;
                    __nv_bfloat16 hx = __float2bfloat16(vx);
                    __nv_bfloat16 hy = __float2bfloat16(vy);
                    __nv_bfloat16 lx = __float2bfloat16(vx - __bfloat162float(hx));
                    __nv_bfloat16 ly = __float2bfloat16(vy - __bfloat162float(hy));
                    *(__nv_bfloat162*)(Chi + idx) = __halves2bfloat162(hx, hy);
                    *(__nv_bfloat162*)(Clo + idx) = __halves2bfloat162(lx, ly);
                }
            }
        }
    }
}

// ---------------------------------------------------------------------------
// Flash attention on tensor cores, split bf16 (3-term) for QK and PV.
//   CTA: 128 q-rows of one (b,h); 8 warps x 16 rows. KV chunks of 64,
//   double-buffered cp.async. Softmax fp32 on MMA C-fragments.
//   Output: split bf16 hi/lo in [B,S,E].
// ---------------------------------------------------------------------------
#define FROWB 144                     // 64 bf16 + 8 pad
#define F_KH  0
#define F_KL  9216
#define F_VH  18432
#define F_VL  27648
#define F_STAGE 36864
#define FLASH_SMEM (2 * F_STAGE)      // 73728

__global__ void __launch_bounds__(256, 1)
flash_mma(const __nv_bfloat16* __restrict__ Qhi, const __nv_bfloat16* __restrict__ Qlo,
          const __nv_bfloat16* __restrict__ Khi, const __nv_bfloat16* __restrict__ Klo,
          const __nv_bfloat16* __restrict__ Vhi, const __nv_bfloat16* __restrict__ Vlo,
          __nv_bfloat16* __restrict__ Ohi, __nv_bfloat16* __restrict__ Olo)
{
    extern __shared__ char smem[];
    const uint32_t sb = smem_u32(smem);
    const int tid = threadIdx.x;
    const int wid = tid >> 5;
    const int lid = tid & 31;
    const int bh  = blockIdx.y;
    const int b   = bh >> 4;
    const int h   = bh & 15;
    const int q0  = blockIdx.x * 128;

    const __nv_bfloat16* Qh_g = Qhi + ((size_t)bh * S_LEN + q0) * HD;
    const __nv_bfloat16* Ql_g = Qlo + ((size_t)bh * S_LEN + q0) * HD;
    const __nv_bfloat16* Kh_g = Khi + (size_t)bh * S_LEN * HD;
    const __nv_bfloat16* Kl_g = Klo + (size_t)bh * S_LEN * HD;
    const __nv_bfloat16* Vh_g = Vhi + (size_t)bh * S_LEN * HD;
    const __nv_bfloat16* Vl_g = Vlo + (size_t)bh * S_LEN * HD;

    // ---- stage Q (128 x 64) hi/lo into buf0, ldmatrix to registers ----
    {
        int row = tid >> 1;
#pragma unroll
        for (int t = 0; t < 4; t++) {
            int seg = (tid & 1) * 4 + t;
            *(uint4*)(smem + F_KH + row * FROWB + seg * 16) =
                *(const uint4*)(Qh_g + (size_t)row * HD + seg * 8);
            *(uint4*)(smem + F_VH + row * FROWB + seg * 16) =
                *(const uint4*)(Ql_g + (size_t)row * HD + seg * 8);
        }
    }
    __syncthreads();

    uint32_t qh[4][4], ql[4][4];
    {
        const int a_row = wid * 16 + (lid & 15);
        const int a_kh  = (lid >> 4) * 16;
#pragma unroll
        for (int ks = 0; ks < 4; ks++) {
            uint32_t ra = a_row * FROWB + ks * 32 + a_kh;
            ldm_x4(qh[ks], sb + F_KH + ra);
            ldm_x4(ql[ks], sb + F_VH + ra);
        }
    }
    __syncthreads();

    // ---- KV staging ----
    const int s_row = tid >> 2;        // 0..63
    auto stage = [&](int c) {
        const uint32_t base = sb + (c & 1) * F_STAGE;
        const size_t gbase = (size_t)(c * 64 + s_row) * HD;
#pragma unroll
        for (int t = 0; t < 2; t++) {
            int seg = (tid & 3) + t * 4;
            uint32_t so = s_row * FROWB + seg * 16;
            const size_t go = gbase + seg * 8;
            cp_async16(base + F_KH + so, Kh_g + go);
            cp_async16(base + F_KL + so, Kl_g + go);
            cp_async16(base + F_VH + so, Vh_g + go);
            cp_async16(base + F_VL + so, Vl_g + go);
        }
        CP_COMMIT();
    };

    float o[8][4];
#pragma unroll
    for (int ni = 0; ni < 8; ni++)
#pragma unroll
        for (int j = 0; j < 4; j++) o[ni][j] = 0.0f;
    float m0 = -1e30f, m1 = -1e30f, l0 = 0.0f, l1 = 0.0f;

    const int b_row = lid & 7;
    const int b_kh  = ((lid >> 3) & 1) * 16;
    const int v_row = lid & 15;

    stage(0);

#pragma unroll 1
    for (int c = 0; c < S_LEN / 64; c++) {
        if (c + 1 < S_LEN / 64) { stage(c + 1); CP_WAIT(1); }
        else                    { CP_WAIT(0); }
        __syncthreads();
        const uint32_t bufb = sb + (c & 1) * F_STAGE;

        // ---- scores: S = Qh·Kh + Qh·Kl + Ql·Kh ----
        float sc[8][4];
#pragma unroll
        for (int ni = 0; ni < 8; ni++)
#pragma unroll
            for (int j = 0; j < 4; j++) sc[ni][j] = 0.0f;

#pragma unroll
        for (int ks = 0; ks < 4; ks++) {
            const uint32_t kso = ks * 32 + b_kh;
#pragma unroll
            for (int ni = 0; ni < 8; ni++) {
                uint32_t kh[2], kl[2];
                uint32_t rb = (ni * 8 + b_row) * FROWB + kso;
                ldm_x2(kh, bufb + F_KH + rb);
                ldm_x2(kl, bufb + F_KL + rb);
                mma_bf16(sc[ni], qh[ks], kh);
                mma_bf16(sc[ni], qh[ks], kl);
                mma_bf16(sc[ni], ql[ks], kh);
            }
        }

        // ---- online softmax (scale 0.125 folded into exp) ----
        float mx0 = -1e30f, mx1 = -1e30f;
#pragma unroll
        for (int ni = 0; ni < 8; ni++) {
            mx0 = fmaxf(mx0, fmaxf(sc[ni][0], sc[ni][1]));
            mx1 = fmaxf(mx1, fmaxf(sc[ni][2], sc[ni][3]));
        }
        mx0 *= 0.125f; mx1 *= 0.125f;
        mx0 = fmaxf(mx0, __shfl_xor_sync(~0u, mx0, 1));
        mx0 = fmaxf(mx0, __shfl_xor_sync(~0u, mx0, 2));
        mx1 = fmaxf(mx1, __shfl_xor_sync(~0u, mx1, 1));
        mx1 = fmaxf(mx1, __shfl_xor_sync(~0u, mx1, 2));
        float mn0 = fmaxf(m0, mx0), mn1 = fmaxf(m1, mx1);
        float corr0 = __expf(m0 - mn0), corr1 = __expf(m1 - mn1);
        m0 = mn0; m1 = mn1;

        float s0 = 0.0f, s1 = 0.0f;
#pragma unroll
        for (int ni = 0; ni < 8; ni++) {
            sc[ni][0] = __expf(fmaf(sc[ni][0], 0.125f, -mn0));
            sc[ni][1] = __expf(fmaf(sc[ni][1], 0.125f, -mn0));
            sc[ni][2] = __expf(fmaf(sc[ni][2], 0.125f, -mn1));
            sc[ni][3] = __expf(fmaf(sc[ni][3], 0.125f, -mn1));
            s0 += sc[ni][0] + sc[ni][1];
            s1 += sc[ni][2] + sc[ni][3];
        }
        s0 += __shfl_xor_sync(~0u, s0, 1);
        s0 += __shfl_xor_sync(~0u, s0, 2);
        s1 += __shfl_xor_sync(~0u, s1, 1);
        s1 += __shfl_xor_sync(~0u, s1, 2);
        l0 = l0 * corr0 + s0;
        l1 = l1 * corr1 + s1;

#pragma unroll
        for (int ni = 0; ni < 8; ni++) {
            o[ni][0] *= corr0; o[ni][1] *= corr0;
            o[ni][2] *= corr1; o[ni][3] *= corr1;
        }

        // ---- pack P into A-fragments (hi/lo) ----
        uint32_t ph[4][4], pl[4][4];
#pragma unroll
        for (int kk = 0; kk < 4; kk++) {
            float p00 = sc[2 * kk][0],     p01 = sc[2 * kk][1];
            float p02 = sc[2 * kk][2],     p03 = sc[2 * kk][3];
            float p10 = sc[2 * kk + 1][0], p11 = sc[2 * kk + 1][1];
            float p12 = sc[2 * kk + 1][2], p13 = sc[2 * kk + 1][3];
            __nv_bfloat16 h00 = __float2bfloat16(p00), h01 = __float2bfloat16(p01);
            __nv_bfloat16 h02 = __float2bfloat16(p02), h03 = __float2bfloat16(p03);
            __nv_bfloat16 h10 = __float2bfloat16(p10), h11 = __float2bfloat16(p11);
            __nv_bfloat16 h12 = __float2bfloat16(p12), h13 = __float2bfloat16(p13);
            ph[kk][0] = pack_bf16x2(p00, p01);
            ph[kk][1] = pack_bf16x2(p02, p03);
            ph[kk][2] = pack_bf16x2(p10, p11);
            ph[kk][3] = pack_bf16x2(p12, p13);
            pl[kk][0] = pack_bf16x2(p00 - __bfloat162float(h00), p01 - __bfloat162float(h01));
            pl[kk][1] = pack_bf16x2(p02 - __bfloat162float(h02), p03 - __bfloat162float(h03));
            pl[kk][2] = pack_bf16x2(p10 - __bfloat162float(h10), p11 - __bfloat162float(h11));
            pl[kk][3] = pack_bf16x2(p12 - __bfloat162float(h12), p13 - __bfloat162float(h13));
        }

        // ---- O += Ph·Vh + Ph·Vl + Pl·Vh ----
#pragma unroll
        for (int ks = 0; ks < 4; ks++) {
#pragma unroll
            for (int ni = 0; ni < 8; ni++) {
                uint32_t vh[2], vl[2];
                uint32_t rv = (ks * 16 + v_row) * FROWB + ni * 16;
                ldm_x2_t(vh, bufb + F_VH + rv);
                ldm_x2_t(vl, bufb + F_VL + rv);
                mma_bf16(o[ni], ph[ks], vh);
                mma_bf16(o[ni], ph[ks], vl);
                mma_bf16(o[ni], pl[ks], vh);
            }
        }
        __syncthreads();
    }

    // ---- epilogue: normalize, split, store [B,S,E] ----
    const int g   = lid >> 2;
    const int tig = lid & 3;
    const float inv0 = 1.0f / l0, inv1 = 1.0f / l1;
#pragma unroll
    for (int half = 0; half < 2; half++) {
        int s = q0 + wid * 16 + g + half * 8;
        float inv = half ? inv1 : inv0;
        size_t rowbase = ((size_t)(b * S_LEN + s)) * EMB + h * HD;
#pragma unroll
        for (int ni = 0; ni < 8; ni++) {
            float vx = o[ni][half * 2 + 0] * inv;
            float vy = o[ni][half * 2 + 1] * inv;
            __nv_bfloat16 hx = __float2bfloat16(vx);
            __nv_bfloat16 hy = __float2bfloat16(vy);
            __nv_bfloat16 lx = __float2bfloat16(vx - __bfloat162float(hx));
            __nv_bfloat16 ly = __float2bfloat16(vy - __bfloat162float(hy));
            size_t idx = rowbase + ni * 8 + tig * 2;
            *(__nv_bfloat162*)(Ohi + idx) = __halves2bfloat162(hx, hy);
            *(__nv_bfloat162*)(Olo + idx) = __halves2bfloat162(lx, ly);
        }
    }
}

// ---------------------------------------------------------------------------
// Launch
// ---------------------------------------------------------------------------
extern "C" void kernel_launch(void* const* d_in, const int* in_sizes, int n_in,
                              void* d_out, int out_size)
{
    const float* x  = (const float*)d_in[0];
    const float* Wq = (const float*)d_in[1];
    const float* bq = (const float*)d_in[2];
    const float* Wk = (const float*)d_in[3];
    const float* bk = (const float*)d_in[4];
    const float* Wv = (const float*)d_in[5];
    const float* bv = (const float*)d_in[6];
    const float* Wo = (const float*)d_in[7];
    const float* bo = (const float*)d_in[8];
    float* out = (float*)d_out;

    __nv_bfloat16 *xhi, *xlo, *whi, *wlo, *ahi, *alo;
    __nv_bfloat16 *qhi, *qlo, *khi, *klo, *vhi, *vlo;
    cudaGetSymbolAddress((void**)&xhi, g_xhi);
    cudaGetSymbolAddress((void**)&xlo, g_xlo);
    cudaGetSymbolAddress((void**)&whi, g_whi);
    cudaGetSymbolAddress((void**)&wlo, g_wlo);
    cudaGetSymbolAddress((void**)&ahi, g_ahi);
    cudaGetSymbolAddress((void**)&alo, g_alo);
    cudaGetSymbolAddress((void**)&qhi, g_qhi);
    cudaGetSymbolAddress((void**)&qlo, g_qlo);
    cudaGetSymbolAddress((void**)&khi, g_khi);
    cudaGetSymbolAddress((void**)&klo, g_klo);
    cudaGetSymbolAddress((void**)&vhi, g_vhi);
    cudaGetSymbolAddress((void**)&vlo, g_vlo);

    cudaFuncSetAttribute(gemm_mma<0>, cudaFuncAttributeMaxDynamicSharedMemorySize, GEMM_SMEM);
    cudaFuncSetAttribute(gemm_mma<1>, cudaFuncAttributeMaxDynamicSharedMemorySize, GEMM_SMEM);
    cudaFuncSetAttribute(flash_mma,   cudaFuncAttributeMaxDynamicSharedMemorySize, FLASH_SMEM);

    const int XN4 = M_TOT * EMB / 4;
    const int WN4 = EMB * EMB / 4;
    const size_t WSZ = (size_t)EMB * EMB;

    convert_split<<<(XN4 + 255) / 256, 256>>>((const float4*)x,
        (__nv_bfloat162*)xhi, (__nv_bfloat162*)xlo, XN4);
    convert_split<<<(WN4 + 255) / 256, 256>>>((const float4*)Wq,
        (__nv_bfloat162*)(whi + 0 * WSZ), (__nv_bfloat162*)(wlo + 0 * WSZ), WN4);
    convert_split<<<(WN4 + 255) / 256, 256>>>((const float4*)Wk,
        (__nv_bfloat162*)(whi + 1 * WSZ), (__nv_bfloat162*)(wlo + 1 * WSZ), WN4);
    convert_split<<<(WN4 + 255) / 256, 256>>>((const float4*)Wv,
        (__nv_bfloat162*)(whi + 2 * WSZ), (__nv_bfloat162*)(wlo + 2 * WSZ), WN4);
    convert_split<<<(WN4 + 255) / 256, 256>>>((const float4*)Wo,
        (__nv_bfloat162*)(whi + 3 * WSZ), (__nv_bfloat162*)(wlo + 3 * WSZ), WN4);

    dim3 gg(EMB / 128, M_TOT / 128);   // (8, 64)
    gemm_mma<1><<<gg, 256, GEMM_SMEM>>>(xhi, xlo, whi + 0 * WSZ, wlo + 0 * WSZ, bq,
                                        nullptr, qhi, qlo);
    gemm_mma<1><<<gg, 256, GEMM_SMEM>>>(xhi, xlo, whi + 1 * WSZ, wlo + 1 * WSZ, bk,
                                        nullptr, khi, klo);
    gemm_mma<1><<<gg, 256, GEMM_SMEM>>>(xhi, xlo, whi + 2 * WSZ, wlo + 2 * WSZ, bv,
                                        nullptr, vhi, vlo);

    dim3 ga(S_LEN / 128, BH);          // (16, 64)
    flash_mma<<<ga, 256, FLASH_SMEM>>>(qhi, qlo, khi, klo, vhi, vlo, ahi, alo);

    gemm_mma<0><<<gg, 256, GEMM_SMEM>>>(ahi, alo, whi + 3 * WSZ, wlo + 3 * WSZ, bo,
                                        out, nullptr, nullptr);
}

// round 6
// speedup vs baseline: 3.2199x; 1.0314x over previous
#include <cuda_runtime.h>
#include <cuda_bf16.h>
#include <cstdint>

#define BATCH 4
#define S_LEN 2048
#define EMB   1024
#define NH    16
#define HD    64
#define M_TOT (BATCH * S_LEN)   // 8192
#define BH    (BATCH * NH)      // 64
#define WSZ   ((size_t)EMB * EMB)

// ---------------------------------------------------------------------------
// Scratch (device globals — no allocation allowed)
// ---------------------------------------------------------------------------
__device__ __nv_bfloat16 g_xhi[(size_t)M_TOT * EMB];
__device__ __nv_bfloat16 g_xlo[(size_t)M_TOT * EMB];
__device__ __nv_bfloat16 g_whi[4][WSZ];
__device__ __nv_bfloat16 g_wlo[4][WSZ];
__device__ __nv_bfloat16 g_qhi[(size_t)BH * S_LEN * HD];
__device__ __nv_bfloat16 g_qlo[(size_t)BH * S_LEN * HD];
__device__ __nv_bfloat16 g_khi[(size_t)BH * S_LEN * HD];
__device__ __nv_bfloat16 g_klo[(size_t)BH * S_LEN * HD];
__device__ __nv_bfloat16 g_vhi[(size_t)BH * S_LEN * HD];
__device__ __nv_bfloat16 g_vlo[(size_t)BH * S_LEN * HD];
__device__ __nv_bfloat16 g_ahi[(size_t)M_TOT * EMB];
__device__ __nv_bfloat16 g_alo[(size_t)M_TOT * EMB];

// ---------------------------------------------------------------------------
// helpers
// ---------------------------------------------------------------------------
__device__ __forceinline__ uint32_t smem_u32(const void* p) {
    uint32_t a;
    asm("{ .reg .u64 t; cvta.to.shared.u64 t, %1; cvt.u32.u64 %0, t; }"
        : "=r"(a) : "l"(p));
    return a;
}
__device__ __forceinline__ void cp_async16(uint32_t dst, const void* src) {
    asm volatile("cp.async.cg.shared.global [%0], [%1], 16;"
                 :: "r"(dst), "l"(__cvta_generic_to_global(src)) : "memory");
}
#define CP_COMMIT()  asm volatile("cp.async.commit_group;" ::: "memory")
#define CP_WAIT(n)   asm volatile("cp.async.wait_group %0;" :: "n"(n) : "memory")

__device__ __forceinline__ void ldm_x4(uint32_t* r, uint32_t addr) {
    asm volatile("ldmatrix.sync.aligned.m8n8.x4.shared.b16 {%0,%1,%2,%3}, [%4];"
                 : "=r"(r[0]), "=r"(r[1]), "=r"(r[2]), "=r"(r[3]) : "r"(addr));
}
__device__ __forceinline__ void ldm_x2(uint32_t* r, uint32_t addr) {
    asm volatile("ldmatrix.sync.aligned.m8n8.x2.shared.b16 {%0,%1}, [%2];"
                 : "=r"(r[0]), "=r"(r[1]) : "r"(addr));
}
__device__ __forceinline__ void ldm_x2_t(uint32_t* r, uint32_t addr) {
    asm volatile("ldmatrix.sync.aligned.m8n8.x2.trans.shared.b16 {%0,%1}, [%2];"
                 : "=r"(r[0]), "=r"(r[1]) : "r"(addr));
}
__device__ __forceinline__ void mma_bf16(float* c, const uint32_t* a, const uint32_t* b) {
    asm volatile(
        "mma.sync.aligned.m16n8k16.row.col.f32.bf16.bf16.f32 "
        "{%0,%1,%2,%3}, {%4,%5,%6,%7}, {%8,%9}, {%0,%1,%2,%3};"
        : "+f"(c[0]), "+f"(c[1]), "+f"(c[2]), "+f"(c[3])
        : "r"(a[0]), "r"(a[1]), "r"(a[2]), "r"(a[3]), "r"(b[0]), "r"(b[1]));
}
__device__ __forceinline__ uint32_t pack_bf16x2(float lo, float hi) {
    uint32_t r;
    asm("cvt.rn.bf16x2.f32 %0, %1, %2;" : "=r"(r) : "f"(hi), "f"(lo));
    return r;
}

// ---------------------------------------------------------------------------
// single fused convert: x + 4 weights -> bf16 hi/lo
// ---------------------------------------------------------------------------
#define N4X (M_TOT * EMB / 4)     // 2097152
#define N4W (EMB * EMB / 4)       // 262144 = 2^18
#define N4ALL (N4X + 4 * N4W)     // 3145728

__global__ void __launch_bounds__(256)
convert_all(const float4* __restrict__ x,
            const float4* __restrict__ Wq, const float4* __restrict__ Wk,
            const float4* __restrict__ Wv, const float4* __restrict__ Wo,
            __nv_bfloat16* __restrict__ xhi, __nv_bfloat16* __restrict__ xlo,
            __nv_bfloat16* __restrict__ whi, __nv_bfloat16* __restrict__ wlo)
{
    int i = blockIdx.x * 256 + threadIdx.x;
    if (i >= N4ALL) return;

    const float4* in;
    __nv_bfloat16 *hp, *lp;
    int idx;
    if (i < N4X) {
        in = x; hp = xhi; lp = xlo; idx = i;
    } else {
        int j = i - N4X;
        int w = j >> 18;
        idx = j & (N4W - 1);
        in = (w == 0) ? Wq : (w == 1) ? Wk : (w == 2) ? Wv : Wo;
        hp = whi + (size_t)w * WSZ;
        lp = wlo + (size_t)w * WSZ;
    }
    float4 v = in[idx];
    __nv_bfloat16 h0 = __float2bfloat16(v.x);
    __nv_bfloat16 h1 = __float2bfloat16(v.y);
    __nv_bfloat16 h2 = __float2bfloat16(v.z);
    __nv_bfloat16 h3 = __float2bfloat16(v.w);
    __nv_bfloat16 l0 = __float2bfloat16(v.x - __bfloat162float(h0));
    __nv_bfloat16 l1 = __float2bfloat16(v.y - __bfloat162float(h1));
    __nv_bfloat16 l2 = __float2bfloat16(v.z - __bfloat162float(h2));
    __nv_bfloat16 l3 = __float2bfloat16(v.w - __bfloat162float(h3));
    __nv_bfloat162* h2p = (__nv_bfloat162*)hp;
    __nv_bfloat162* l2p = (__nv_bfloat162*)lp;
    h2p[2 * idx + 0] = __halves2bfloat162(h0, h1);
    h2p[2 * idx + 1] = __halves2bfloat162(h2, h3);
    l2p[2 * idx + 0] = __halves2bfloat162(l0, l1);
    l2p[2 * idx + 1] = __halves2bfloat162(l2, l3);
}

// ---------------------------------------------------------------------------
// GEMM common pieces: 128x128 CTA tile, BK=32, 3-stage cp.async pipeline
// ---------------------------------------------------------------------------
#define ROWB 80
#define TILE_B (128 * ROWB)
#define ST_AH 0
#define ST_AL (1 * TILE_B)
#define ST_BH (2 * TILE_B)
#define ST_BL (3 * TILE_B)
#define STAGE_B (4 * TILE_B)          // 40960
#define GEMM_SMEM (3 * STAGE_B)       // 122880
#define KITER (EMB / 32)              // 32

#define GEMM_MAINLOOP()                                                        \
    float acc[4][4][4];                                                        \
    _Pragma("unroll")                                                          \
    for (int i = 0; i < 4; i++)                                                \
        _Pragma("unroll")                                                      \
        for (int j = 0; j < 4; j++)                                            \
            _Pragma("unroll")                                                  \
            for (int k = 0; k < 4; k++) acc[i][j][k] = 0.0f;                   \
    const int a_row = wm * 64 + (lid & 15);                                    \
    const int a_kh  = (lid >> 4) * 16;                                         \
    const int b_row = wn * 32 + (lid & 7);                                     \
    const int b_kh  = ((lid >> 3) & 1) * 16;                                   \
    stage(0, 0); stage(1, 1);                                                  \
    _Pragma("unroll 1")                                                        \
    for (int kc = 0; kc < KITER; kc++) {                                       \
        if (kc + 1 < KITER) { CP_WAIT(1); } else { CP_WAIT(0); }               \
        __syncthreads();                                                       \
        if (kc + 2 < KITER) stage((kc + 2) % 3, kc + 2);                       \
        const uint32_t bufb = sb + (kc % 3) * STAGE_B;                         \
        _Pragma("unroll")                                                      \
        for (int ks = 0; ks < 2; ks++) {                                       \
            const uint32_t kso = ks * 32;                                      \
            uint32_t ah[4][4], al[4][4], bhf[4][2], blf[4][2];                 \
            _Pragma("unroll")                                                  \
            for (int mi = 0; mi < 4; mi++) {                                   \
                uint32_t ra = (a_row + mi * 16) * ROWB + kso + a_kh;           \
                ldm_x4(ah[mi], bufb + ST_AH + ra);                             \
                ldm_x4(al[mi], bufb + ST_AL + ra);                             \
            }                                                                  \
            _Pragma("unroll")                                                  \
            for (int ni = 0; ni < 4; ni++) {                                   \
                uint32_t rb = (b_row + ni * 8) * ROWB + kso + b_kh;            \
                ldm_x2(bhf[ni], bufb + ST_BH + rb);                            \
                ldm_x2(blf[ni], bufb + ST_BL + rb);                            \
            }                                                                  \
            _Pragma("unroll")                                                  \
            for (int mi = 0; mi < 4; mi++)                                     \
                _Pragma("unroll")                                              \
                for (int ni = 0; ni < 4; ni++) {                               \
                    mma_bf16(acc[mi][ni], ah[mi], bhf[ni]);                    \
                    mma_bf16(acc[mi][ni], ah[mi], blf[ni]);                    \
                    mma_bf16(acc[mi][ni], al[mi], bhf[ni]);                    \
                }                                                              \
        }                                                                      \
    }

// fused QKV GEMM: grid (24, 64); bn>>3 selects {Q,K,V}
__global__ void __launch_bounds__(256)
gemm_qkv(const __nv_bfloat16* __restrict__ Ahi, const __nv_bfloat16* __restrict__ Alo,
         const __nv_bfloat16* __restrict__ Whi, const __nv_bfloat16* __restrict__ Wlo,
         const float* __restrict__ bq, const float* __restrict__ bk,
         const float* __restrict__ bv,
         __nv_bfloat16* __restrict__ qhi, __nv_bfloat16* __restrict__ qlo,
         __nv_bfloat16* __restrict__ khi, __nv_bfloat16* __restrict__ klo,
         __nv_bfloat16* __restrict__ vhi, __nv_bfloat16* __restrict__ vlo)
{
    extern __shared__ char smem[];
    const uint32_t sb = smem_u32(smem);
    const int tid = threadIdx.x;
    const int wid = tid >> 5;
    const int lid = tid & 31;
    const int bn  = blockIdx.x;
    const int w   = bn >> 3;
    const int tm  = blockIdx.y * 128;
    const int tn  = (bn & 7) * 128;
    const int wm  = wid >> 2;
    const int wn  = wid & 3;

    const float* bias = (w == 0) ? bq : (w == 1) ? bk : bv;
    __nv_bfloat16* Chi = (w == 0) ? qhi : (w == 1) ? khi : vhi;
    __nv_bfloat16* Clo = (w == 0) ? qlo : (w == 1) ? klo : vlo;

    const int r0 = tid >> 2;
    const int c16 = (tid & 3) * 16;
    const __nv_bfloat16* gA[2] = { Ahi + (size_t)tm * EMB, Alo + (size_t)tm * EMB };
    const __nv_bfloat16* gB[2] = { Whi + (size_t)w * WSZ + (size_t)tn * EMB,
                                   Wlo + (size_t)w * WSZ + (size_t)tn * EMB };

    auto stage = [&](int buf, int kc) {
        const uint32_t base = sb + buf * STAGE_B;
        const int gcol = kc * 32 + (c16 >> 1);
#pragma unroll
        for (int t = 0; t < 2; t++) {
            int row = r0 + t * 64;
            uint32_t so = row * ROWB + c16;
            cp_async16(base + ST_AH + so, gA[0] + (size_t)row * EMB + gcol);
            cp_async16(base + ST_AL + so, gA[1] + (size_t)row * EMB + gcol);
            cp_async16(base + ST_BH + so, gB[0] + (size_t)row * EMB + gcol);
            cp_async16(base + ST_BL + so, gB[1] + (size_t)row * EMB + gcol);
        }
        CP_COMMIT();
    };

    GEMM_MAINLOOP()

    // epilogue: split bf16, scatter to [B,H,S,D]
    const int g   = lid >> 2;
    const int tig = lid & 3;
#pragma unroll
    for (int ni = 0; ni < 4; ni++) {
        const int n = tn + wn * 32 + ni * 8 + tig * 2;
        const float b0 = bias[n], b1 = bias[n + 1];
        const int hh = n >> 6, dd = n & 63;
#pragma unroll
        for (int mi = 0; mi < 4; mi++) {
#pragma unroll
            for (int half = 0; half < 2; half++) {
                int m = tm + wm * 64 + mi * 16 + g + half * 8;
                float vx = acc[mi][ni][half * 2 + 0] + b0;
                float vy = acc[mi][ni][half * 2 + 1] + b1;
                int bb = m >> 11, ss = m & 2047;
                size_t idx = (((size_t)(bb * NH + hh) * S_LEN) + ss) * HD + dd;
                __nv_bfloat16 hx = __float2bfloat16(vx);
                __nv_bfloat16 hy = __float2bfloat16(vy);
                __nv_bfloat16 lx = __float2bfloat16(vx - __bfloat162float(hx));
                __nv_bfloat16 ly = __float2bfloat16(vy - __bfloat162float(hy));
                *(__nv_bfloat162*)(Chi + idx) = __halves2bfloat162(hx, hy);
                *(__nv_bfloat162*)(Clo + idx) = __halves2bfloat162(lx, ly);
            }
        }
    }
}

// output projection GEMM: fp32 C row-major
__global__ void __launch_bounds__(256)
gemm_out(const __nv_bfloat16* __restrict__ Ahi, const __nv_bfloat16* __restrict__ Alo,
         const __nv_bfloat16* __restrict__ Bhi, const __nv_bfloat16* __restrict__ Blo,
         const float* __restrict__ bias, float* __restrict__ C)
{
    extern __shared__ char smem[];
    const uint32_t sb = smem_u32(smem);
    const int tid = threadIdx.x;
    const int wid = tid >> 5;
    const int lid = tid & 31;
    const int tm  = blockIdx.y * 128;
    const int tn  = blockIdx.x * 128;
    const int wm  = wid >> 2;
    const int wn  = wid & 3;

    const int r0 = tid >> 2;
    const int c16 = (tid & 3) * 16;
    const __nv_bfloat16* gA[2] = { Ahi + (size_t)tm * EMB, Alo + (size_t)tm * EMB };
    const __nv_bfloat16* gB[2] = { Bhi + (size_t)tn * EMB, Blo + (size_t)tn * EMB };

    auto stage = [&](int buf, int kc) {
        const uint32_t base = sb + buf * STAGE_B;
        const int gcol = kc * 32 + (c16 >> 1);
#pragma unroll
        for (int t = 0; t < 2; t++) {
            int row = r0 + t * 64;
            uint32_t so = row * ROWB + c16;
            cp_async16(base + ST_AH + so, gA[0] + (size_t)row * EMB + gcol);
            cp_async16(base + ST_AL + so, gA[1] + (size_t)row * EMB + gcol);
            cp_async16(base + ST_BH + so, gB[0] + (size_t)row * EMB + gcol);
            cp_async16(base + ST_BL + so, gB[1] + (size_t)row * EMB + gcol);
        }
        CP_COMMIT();
    };

    GEMM_MAINLOOP()

    const int g   = lid >> 2;
    const int tig = lid & 3;
#pragma unroll
    for (int ni = 0; ni < 4; ni++) {
        const int n = tn + wn * 32 + ni * 8 + tig * 2;
        const float b0 = bias[n], b1 = bias[n + 1];
#pragma unroll
        for (int mi = 0; mi < 4; mi++) {
#pragma unroll
            for (int half = 0; half < 2; half++) {
                int m = tm + wm * 64 + mi * 16 + g + half * 8;
                float2 v;
                v.x = acc[mi][ni][half * 2 + 0] + b0;
                v.y = acc[mi][ni][half * 2 + 1] + b1;
                *(float2*)(C + (size_t)m * EMB + n) = v;
            }
        }
    }
}

// ---------------------------------------------------------------------------
// Flash attention on tensor cores, split bf16, 3-stage cp.async pipeline
// ---------------------------------------------------------------------------
#define FROWB 144
#define F_KH  0
#define F_KL  9216
#define F_VH  18432
#define F_VL  27648
#define F_STAGE 36864
#define FLASH_SMEM (3 * F_STAGE)      // 110592
#define NCHUNK (S_LEN / 64)           // 32

__global__ void __launch_bounds__(256, 1)
flash_mma(const __nv_bfloat16* __restrict__ Qhi, const __nv_bfloat16* __restrict__ Qlo,
          const __nv_bfloat16* __restrict__ Khi, const __nv_bfloat16* __restrict__ Klo,
          const __nv_bfloat16* __restrict__ Vhi, const __nv_bfloat16* __restrict__ Vlo,
          __nv_bfloat16* __restrict__ Ohi, __nv_bfloat16* __restrict__ Olo)
{
    extern __shared__ char smem[];
    const uint32_t sb = smem_u32(smem);
    const int tid = threadIdx.x;
    const int wid = tid >> 5;
    const int lid = tid & 31;
    const int bh  = blockIdx.y;
    const int b   = bh >> 4;
    const int h   = bh & 15;
    const int q0  = blockIdx.x * 128;

    const __nv_bfloat16* Qh_g = Qhi + ((size_t)bh * S_LEN + q0) * HD;
    const __nv_bfloat16* Ql_g = Qlo + ((size_t)bh * S_LEN + q0) * HD;
    const __nv_bfloat16* Kh_g = Khi + (size_t)bh * S_LEN * HD;
    const __nv_bfloat16* Kl_g = Klo + (size_t)bh * S_LEN * HD;
    const __nv_bfloat16* Vh_g = Vhi + (size_t)bh * S_LEN * HD;
    const __nv_bfloat16* Vl_g = Vlo + (size_t)bh * S_LEN * HD;

    // ---- stage Q (128 x 64) hi/lo into buf0 region, ldmatrix to registers ----
    {
        int row = tid >> 1;
#pragma unroll
        for (int t = 0; t < 4; t++) {
            int seg = (tid & 1) * 4 + t;
            *(uint4*)(smem + F_KH + row * FROWB + seg * 16) =
                *(const uint4*)(Qh_g + (size_t)row * HD + seg * 8);
            *(uint4*)(smem + F_VH + row * FROWB + seg * 16) =
                *(const uint4*)(Ql_g + (size_t)row * HD + seg * 8);
        }
    }
    __syncthreads();

    uint32_t qh[4][4], ql[4][4];
    {
        const int a_row = wid * 16 + (lid & 15);
        const int a_kh  = (lid >> 4) * 16;
#pragma unroll
        for (int ks = 0; ks < 4; ks++) {
            uint32_t ra = a_row * FROWB + ks * 32 + a_kh;
            ldm_x4(qh[ks], sb + F_KH + ra);
            ldm_x4(ql[ks], sb + F_VH + ra);
        }
    }
    __syncthreads();

    // ---- KV staging ----
    const int s_row = tid >> 2;
    auto stage = [&](int c) {
        const uint32_t base = sb + (c % 3) * F_STAGE;
        const size_t gbase = (size_t)(c * 64 + s_row) * HD;
#pragma unroll
        for (int t = 0; t < 2; t++) {
            int seg = (tid & 3) + t * 4;
            uint32_t so = s_row * FROWB + seg * 16;
            const size_t go = gbase + seg * 8;
            cp_async16(base + F_KH + so, Kh_g + go);
            cp_async16(base + F_KL + so, Kl_g + go);
            cp_async16(base + F_VH + so, Vh_g + go);
            cp_async16(base + F_VL + so, Vl_g + go);
        }
        CP_COMMIT();
    };

    float o[8][4];
#pragma unroll
    for (int ni = 0; ni < 8; ni++)
#pragma unroll
        for (int j = 0; j < 4; j++) o[ni][j] = 0.0f;
    float m0 = -1e30f, m1 = -1e30f, l0 = 0.0f, l1 = 0.0f;

    const int b_row = lid & 7;
    const int b_kh  = ((lid >> 3) & 1) * 16;
    const int v_row = lid & 15;

    stage(0); stage(1);

#pragma unroll 1
    for (int c = 0; c < NCHUNK; c++) {
        if (c + 1 < NCHUNK) { CP_WAIT(1); } else { CP_WAIT(0); }
        __syncthreads();
        if (c + 2 < NCHUNK) stage(c + 2);
        const uint32_t bufb = sb + (c % 3) * F_STAGE;

        // ---- scores: S = Qh·Kh + Qh·Kl + Ql·Kh ----
        float sc[8][4];
#pragma unroll
        for (int ni = 0; ni < 8; ni++)
#pragma unroll
            for (int j = 0; j < 4; j++) sc[ni][j] = 0.0f;

#pragma unroll
        for (int ks = 0; ks < 4; ks++) {
            const uint32_t kso = ks * 32 + b_kh;
#pragma unroll
            for (int ni = 0; ni < 8; ni++) {
                uint32_t kh[2], kl[2];
                uint32_t rb = (ni * 8 + b_row) * FROWB + kso;
                ldm_x2(kh, bufb + F_KH + rb);
                ldm_x2(kl, bufb + F_KL + rb);
                mma_bf16(sc[ni], qh[ks], kh);
                mma_bf16(sc[ni], qh[ks], kl);
                mma_bf16(sc[ni], ql[ks], kh);
            }
        }

        // ---- online softmax ----
        float mx0 = -1e30f, mx1 = -1e30f;
#pragma unroll
        for (int ni = 0; ni < 8; ni++) {
            mx0 = fmaxf(mx0, fmaxf(sc[ni][0], sc[ni][1]));
            mx1 = fmaxf(mx1, fmaxf(sc[ni][2], sc[ni][3]));
        }
        mx0 *= 0.125f; mx1 *= 0.125f;
        mx0 = fmaxf(mx0, __shfl_xor_sync(~0u, mx0, 1));
        mx0 = fmaxf(mx0, __shfl_xor_sync(~0u, mx0, 2));
        mx1 = fmaxf(mx1, __shfl_xor_sync(~0u, mx1, 1));
        mx1 = fmaxf(mx1, __shfl_xor_sync(~0u, mx1, 2));
        float mn0 = fmaxf(m0, mx0), mn1 = fmaxf(m1, mx1);
        float corr0 = __expf(m0 - mn0), corr1 = __expf(m1 - mn1);
        m0 = mn0; m1 = mn1;

        float s0 = 0.0f, s1 = 0.0f;
#pragma unroll
        for (int ni = 0; ni < 8; ni++) {
            sc[ni][0] = __expf(fmaf(sc[ni][0], 0.125f, -mn0));
            sc[ni][1] = __expf(fmaf(sc[ni][1], 0.125f, -mn0));
            sc[ni][2] = __expf(fmaf(sc[ni][2], 0.125f, -mn1));
            sc[ni][3] = __expf(fmaf(sc[ni][3], 0.125f, -mn1));
            s0 += sc[ni][0] + sc[ni][1];
            s1 += sc[ni][2] + sc[ni][3];
        }
        s0 += __shfl_xor_sync(~0u, s0, 1);
        s0 += __shfl_xor_sync(~0u, s0, 2);
        s1 += __shfl_xor_sync(~0u, s1, 1);
        s1 += __shfl_xor_sync(~0u, s1, 2);
        l0 = l0 * corr0 + s0;
        l1 = l1 * corr1 + s1;

#pragma unroll
        for (int ni = 0; ni < 8; ni++) {
            o[ni][0] *= corr0; o[ni][1] *= corr0;
            o[ni][2] *= corr1; o[ni][3] *= corr1;
        }

        // ---- pack P into A-fragments (hi/lo) ----
        uint32_t ph[4][4], pl[4][4];
#pragma unroll
        for (int kk = 0; kk < 4; kk++) {
            float p00 = sc[2 * kk][0],     p01 = sc[2 * kk][1];
            float p02 = sc[2 * kk][2],     p03 = sc[2 * kk][3];
            float p10 = sc[2 * kk + 1][0], p11 = sc[2 * kk + 1][1];
            float p12 = sc[2 * kk + 1][2], p13 = sc[2 * kk + 1][3];
            __nv_bfloat16 h00 = __float2bfloat16(p00), h01 = __float2bfloat16(p01);
            __nv_bfloat16 h02 = __float2bfloat16(p02), h03 = __float2bfloat16(p03);
            __nv_bfloat16 h10 = __float2bfloat16(p10), h11 = __float2bfloat16(p11);
            __nv_bfloat16 h12 = __float2bfloat16(p12), h13 = __float2bfloat16(p13);
            ph[kk][0] = pack_bf16x2(p00, p01);
            ph[kk][1] = pack_bf16x2(p02, p03);
            ph[kk][2] = pack_bf16x2(p10, p11);
            ph[kk][3] = pack_bf16x2(p12, p13);
            pl[kk][0] = pack_bf16x2(p00 - __bfloat162float(h00), p01 - __bfloat162float(h01));
            pl[kk][1] = pack_bf16x2(p02 - __bfloat162float(h02), p03 - __bfloat162float(h03));
            pl[kk][2] = pack_bf16x2(p10 - __bfloat162float(h10), p11 - __bfloat162float(h11));
            pl[kk][3] = pack_bf16x2(p12 - __bfloat162float(h12), p13 - __bfloat162float(h13));
        }

        // ---- O += Ph·Vh + Ph·Vl + Pl·Vh ----
#pragma unroll
        for (int ks = 0; ks < 4; ks++) {
#pragma unroll
            for (int ni = 0; ni < 8; ni++) {
                uint32_t vh[2], vl[2];
                uint32_t rv = (ks * 16 + v_row) * FROWB + ni * 16;
                ldm_x2_t(vh, bufb + F_VH + rv);
                ldm_x2_t(vl, bufb + F_VL + rv);
                mma_bf16(o[ni], ph[ks], vh);
                mma_bf16(o[ni], ph[ks], vl);
                mma_bf16(o[ni], pl[ks], vh);
            }
        }
    }

    // ---- epilogue ----
    const int g   = lid >> 2;
    const int tig = lid & 3;
    const float inv0 = 1.0f / l0, inv1 = 1.0f / l1;
#pragma unroll
    for (int half = 0; half < 2; half++) {
        int s = q0 + wid * 16 + g + half * 8;
        float inv = half ? inv1 : inv0;
        size_t rowbase = ((size_t)(b * S_LEN + s)) * EMB + h * HD;
#pragma unroll
        for (int ni = 0; ni < 8; ni++) {
            float vx = o[ni][half * 2 + 0] * inv;
            float vy = o[ni][half * 2 + 1] * inv;
            __nv_bfloat16 hx = __float2bfloat16(vx);
            __nv_bfloat16 hy = __float2bfloat16(vy);
            __nv_bfloat16 lx = __float2bfloat16(vx - __bfloat162float(hx));
            __nv_bfloat16 ly = __float2bfloat16(vy - __bfloat162float(hy));
            size_t idx = rowbase + ni * 8 + tig * 2;
            *(__nv_bfloat162*)(Ohi + idx) = __halves2bfloat162(hx, hy);
            *(__nv_bfloat162*)(Olo + idx) = __halves2bfloat162(lx, ly);
        }
    }
}

// ---------------------------------------------------------------------------
// Launch
// ---------------------------------------------------------------------------
extern "C" void kernel_launch(void* const* d_in, const int* in_sizes, int n_in,
                              void* d_out, int out_size)
{
    const float* x  = (const float*)d_in[0];
    const float* Wq = (const float*)d_in[1];
    const float* bq = (const float*)d_in[2];
    const float* Wk = (const float*)d_in[3];
    const float* bk = (const float*)d_in[4];
    const float* Wv = (const float*)d_in[5];
    const float* bv = (const float*)d_in[6];
    const float* Wo = (const float*)d_in[7];
    const float* bo = (const float*)d_in[8];
    float* out = (float*)d_out;

    __nv_bfloat16 *xhi, *xlo, *whi, *wlo, *ahi, *alo;
    __nv_bfloat16 *qhi, *qlo, *khi, *klo, *vhi, *vlo;
    cudaGetSymbolAddress((void**)&xhi, g_xhi);
    cudaGetSymbolAddress((void**)&xlo, g_xlo);
    cudaGetSymbolAddress((void**)&whi, g_whi);
    cudaGetSymbolAddress((void**)&wlo, g_wlo);
    cudaGetSymbolAddress((void**)&ahi, g_ahi);
    cudaGetSymbolAddress((void**)&alo, g_alo);
    cudaGetSymbolAddress((void**)&qhi, g_qhi);
    cudaGetSymbolAddress((void**)&qlo, g_qlo);
    cudaGetSymbolAddress((void**)&khi, g_khi);
    cudaGetSymbolAddress((void**)&klo, g_klo);
    cudaGetSymbolAddress((void**)&vhi, g_vhi);
    cudaGetSymbolAddress((void**)&vlo, g_vlo);

    cudaFuncSetAttribute(gemm_qkv, cudaFuncAttributeMaxDynamicSharedMemorySize, GEMM_SMEM);
    cudaFuncSetAttribute(gemm_out, cudaFuncAttributeMaxDynamicSharedMemorySize, GEMM_SMEM);
    cudaFuncSetAttribute(flash_mma, cudaFuncAttributeMaxDynamicSharedMemorySize, FLASH_SMEM);

    convert_all<<<(N4ALL + 255) / 256, 256>>>((const float4*)x,
        (const float4*)Wq, (const float4*)Wk, (const float4*)Wv, (const float4*)Wo,
        xhi, xlo, whi, wlo);

    dim3 gq(24, M_TOT / 128);          // fused QKV
    gemm_qkv<<<gq, 256, GEMM_SMEM>>>(xhi, xlo, whi, wlo, bq, bk, bv,
                                     qhi, qlo, khi, klo, vhi, vlo);

    dim3 ga(S_LEN / 128, BH);          // (16, 64)
    flash_mma<<<ga, 256, FLASH_SMEM>>>(qhi, qlo, khi, klo, vhi, vlo, ahi, alo);

    dim3 gg(EMB / 128, M_TOT / 128);   // (8, 64)
    gemm_out<<<gg, 256, GEMM_SMEM>>>(ahi, alo, whi + 3 * WSZ, wlo + 3 * WSZ, bo, out);
}

// round 7
// speedup vs baseline: 3.6828x; 1.1438x over previous
#include <cuda_runtime.h>
#include <cuda_bf16.h>
#include <cstdint>

#define BATCH 4
#define S_LEN 2048
#define EMB   1024
#define NH    16
#define HD    64
#define M_TOT (BATCH * S_LEN)   // 8192
#define BH    (BATCH * NH)      // 64
#define WSZ   ((size_t)EMB * EMB)

// ---------------------------------------------------------------------------
// Scratch (device globals — no allocation allowed)
// ---------------------------------------------------------------------------
__device__ __nv_bfloat16 g_xhi[(size_t)M_TOT * EMB];
__device__ __nv_bfloat16 g_xlo[(size_t)M_TOT * EMB];
__device__ __nv_bfloat16 g_whi[4][WSZ];
__device__ __nv_bfloat16 g_wlo[4][WSZ];
__device__ __nv_bfloat16 g_qhi[(size_t)BH * S_LEN * HD];
__device__ __nv_bfloat16 g_qlo[(size_t)BH * S_LEN * HD];
__device__ __nv_bfloat16 g_khi[(size_t)BH * S_LEN * HD];
__device__ __nv_bfloat16 g_klo[(size_t)BH * S_LEN * HD];
__device__ __nv_bfloat16 g_vhi[(size_t)BH * S_LEN * HD];
__device__ __nv_bfloat16 g_vlo[(size_t)BH * S_LEN * HD];
__device__ __nv_bfloat16 g_ahi[(size_t)M_TOT * EMB];
__device__ __nv_bfloat16 g_alo[(size_t)M_TOT * EMB];

// ---------------------------------------------------------------------------
// helpers
// ---------------------------------------------------------------------------
__device__ __forceinline__ uint32_t smem_u32(const void* p) {
    uint32_t a;
    asm("{ .reg .u64 t; cvta.to.shared.u64 t, %1; cvt.u32.u64 %0, t; }"
        : "=r"(a) : "l"(p));
    return a;
}
__device__ __forceinline__ void cp_async16(uint32_t dst, const void* src) {
    asm volatile("cp.async.cg.shared.global [%0], [%1], 16;"
                 :: "r"(dst), "l"(__cvta_generic_to_global(src)) : "memory");
}
#define CP_COMMIT()  asm volatile("cp.async.commit_group;" ::: "memory")
#define CP_WAIT(n)   asm volatile("cp.async.wait_group %0;" :: "n"(n) : "memory")

__device__ __forceinline__ void ldm_x4(uint32_t* r, uint32_t addr) {
    asm volatile("ldmatrix.sync.aligned.m8n8.x4.shared.b16 {%0,%1,%2,%3}, [%4];"
                 : "=r"(r[0]), "=r"(r[1]), "=r"(r[2]), "=r"(r[3]) : "r"(addr));
}
__device__ __forceinline__ void ldm_x2(uint32_t* r, uint32_t addr) {
    asm volatile("ldmatrix.sync.aligned.m8n8.x2.shared.b16 {%0,%1}, [%2];"
                 : "=r"(r[0]), "=r"(r[1]) : "r"(addr));
}
__device__ __forceinline__ void ldm_x2_t(uint32_t* r, uint32_t addr) {
    asm volatile("ldmatrix.sync.aligned.m8n8.x2.trans.shared.b16 {%0,%1}, [%2];"
                 : "=r"(r[0]), "=r"(r[1]) : "r"(addr));
}
__device__ __forceinline__ void mma_bf16(float* c, const uint32_t* a, const uint32_t* b) {
    asm volatile(
        "mma.sync.aligned.m16n8k16.row.col.f32.bf16.bf16.f32 "
        "{%0,%1,%2,%3}, {%4,%5,%6,%7}, {%8,%9}, {%0,%1,%2,%3};"
        : "+f"(c[0]), "+f"(c[1]), "+f"(c[2]), "+f"(c[3])
        : "r"(a[0]), "r"(a[1]), "r"(a[2]), "r"(a[3]), "r"(b[0]), "r"(b[1]));
}
__device__ __forceinline__ uint32_t pack_bf16x2(float lo, float hi) {
    uint32_t r;
    asm("cvt.rn.bf16x2.f32 %0, %1, %2;" : "=r"(r) : "f"(hi), "f"(lo));
    return r;
}

// ---------------------------------------------------------------------------
// single fused convert: x + 4 weights -> bf16 hi/lo
// ---------------------------------------------------------------------------
#define N4X (M_TOT * EMB / 4)
#define N4W (EMB * EMB / 4)
#define N4ALL (N4X + 4 * N4W)

__global__ void __launch_bounds__(256)
convert_all(const float4* __restrict__ x,
            const float4* __restrict__ Wq, const float4* __restrict__ Wk,
            const float4* __restrict__ Wv, const float4* __restrict__ Wo,
            __nv_bfloat16* __restrict__ xhi, __nv_bfloat16* __restrict__ xlo,
            __nv_bfloat16* __restrict__ whi, __nv_bfloat16* __restrict__ wlo)
{
    int i = blockIdx.x * 256 + threadIdx.x;
    if (i >= N4ALL) return;

    const float4* in;
    __nv_bfloat16 *hp, *lp;
    int idx;
    if (i < N4X) {
        in = x; hp = xhi; lp = xlo; idx = i;
    } else {
        int j = i - N4X;
        int w = j >> 18;
        idx = j & (N4W - 1);
        in = (w == 0) ? Wq : (w == 1) ? Wk : (w == 2) ? Wv : Wo;
        hp = whi + (size_t)w * WSZ;
        lp = wlo + (size_t)w * WSZ;
    }
    float4 v = in[idx];
    __nv_bfloat16 h0 = __float2bfloat16(v.x);
    __nv_bfloat16 h1 = __float2bfloat16(v.y);
    __nv_bfloat16 h2 = __float2bfloat16(v.z);
    __nv_bfloat16 h3 = __float2bfloat16(v.w);
    __nv_bfloat16 l0 = __float2bfloat16(v.x - __bfloat162float(h0));
    __nv_bfloat16 l1 = __float2bfloat16(v.y - __bfloat162float(h1));
    __nv_bfloat16 l2 = __float2bfloat16(v.z - __bfloat162float(h2));
    __nv_bfloat16 l3 = __float2bfloat16(v.w - __bfloat162float(h3));
    __nv_bfloat162* h2p = (__nv_bfloat162*)hp;
    __nv_bfloat162* l2p = (__nv_bfloat162*)lp;
    h2p[2 * idx + 0] = __halves2bfloat162(h0, h1);
    h2p[2 * idx + 1] = __halves2bfloat162(h2, h3);
    l2p[2 * idx + 0] = __halves2bfloat162(l0, l1);
    l2p[2 * idx + 1] = __halves2bfloat162(l2, l3);
}

// ---------------------------------------------------------------------------
// GEMM: 128x128 CTA tile, BK=32, 2-stage cp.async, 2 CTAs/SM
// ---------------------------------------------------------------------------
#define ROWB 80
#define TILE_B (128 * ROWB)
#define ST_AH 0
#define ST_AL (1 * TILE_B)
#define ST_BH (2 * TILE_B)
#define ST_BL (3 * TILE_B)
#define STAGE_B (4 * TILE_B)          // 40960
#define GEMM_SMEM (2 * STAGE_B)       // 81920
#define KITER (EMB / 32)              // 32

#define GEMM_MAINLOOP()                                                        \
    float acc[4][4][4];                                                        \
    _Pragma("unroll")                                                          \
    for (int i = 0; i < 4; i++)                                                \
        _Pragma("unroll")                                                      \
        for (int j = 0; j < 4; j++)                                            \
            _Pragma("unroll")                                                  \
            for (int k = 0; k < 4; k++) acc[i][j][k] = 0.0f;                   \
    const int a_row = wm * 64 + (lid & 15);                                    \
    const int a_kh  = (lid >> 4) * 16;                                         \
    const int b_row = wn * 32 + (lid & 7);                                     \
    const int b_kh  = ((lid >> 3) & 1) * 16;                                   \
    stage(0, 0);                                                               \
    _Pragma("unroll 1")                                                        \
    for (int kc = 0; kc < KITER; kc++) {                                       \
        CP_WAIT(0);                                                            \
        __syncthreads();                                                       \
        if (kc + 1 < KITER) stage((kc + 1) & 1, kc + 1);                       \
        const uint32_t bufb = sb + (kc & 1) * STAGE_B;                         \
        _Pragma("unroll")                                                      \
        for (int ks = 0; ks < 2; ks++) {                                       \
            const uint32_t kso = ks * 32;                                      \
            uint32_t ah[4][4], al[4][4], bhf[4][2], blf[4][2];                 \
            _Pragma("unroll")                                                  \
            for (int mi = 0; mi < 4; mi++) {                                   \
                uint32_t ra = (a_row + mi * 16) * ROWB + kso + a_kh;           \
                ldm_x4(ah[mi], bufb + ST_AH + ra);                             \
                ldm_x4(al[mi], bufb + ST_AL + ra);                             \
            }                                                                  \
            _Pragma("unroll")                                                  \
            for (int ni = 0; ni < 4; ni++) {                                   \
                uint32_t rb = (b_row + ni * 8) * ROWB + kso + b_kh;            \
                ldm_x2(bhf[ni], bufb + ST_BH + rb);                            \
                ldm_x2(blf[ni], bufb + ST_BL + rb);                            \
            }                                                                  \
            _Pragma("unroll")                                                  \
            for (int mi = 0; mi < 4; mi++)                                     \
                _Pragma("unroll")                                              \
                for (int ni = 0; ni < 4; ni++) {                               \
                    mma_bf16(acc[mi][ni], ah[mi], bhf[ni]);                    \
                    mma_bf16(acc[mi][ni], ah[mi], blf[ni]);                    \
                    mma_bf16(acc[mi][ni], al[mi], bhf[ni]);                    \
                }                                                              \
        }                                                                      \
    }

// fused QKV GEMM: grid (24, 64); bn>>3 selects {Q,K,V}
__global__ void __launch_bounds__(256, 2)
gemm_qkv(const __nv_bfloat16* __restrict__ Ahi, const __nv_bfloat16* __restrict__ Alo,
         const __nv_bfloat16* __restrict__ Whi, const __nv_bfloat16* __restrict__ Wlo,
         const float* __restrict__ bq, const float* __restrict__ bk,
         const float* __restrict__ bv,
         __nv_bfloat16* __restrict__ qhi, __nv_bfloat16* __restrict__ qlo,
         __nv_bfloat16* __restrict__ khi, __nv_bfloat16* __restrict__ klo,
         __nv_bfloat16* __restrict__ vhi, __nv_bfloat16* __restrict__ vlo)
{
    extern __shared__ char smem[];
    const uint32_t sb = smem_u32(smem);
    const int tid = threadIdx.x;
    const int wid = tid >> 5;
    const int lid = tid & 31;
    const int bn  = blockIdx.x;
    const int w   = bn >> 3;
    const int tm  = blockIdx.y * 128;
    const int tn  = (bn & 7) * 128;
    const int wm  = wid >> 2;
    const int wn  = wid & 3;

    const float* bias = (w == 0) ? bq : (w == 1) ? bk : bv;
    __nv_bfloat16* Chi = (w == 0) ? qhi : (w == 1) ? khi : vhi;
    __nv_bfloat16* Clo = (w == 0) ? qlo : (w == 1) ? klo : vlo;

    const int r0 = tid >> 2;
    const int c16 = (tid & 3) * 16;
    const __nv_bfloat16* gA[2] = { Ahi + (size_t)tm * EMB, Alo + (size_t)tm * EMB };
    const __nv_bfloat16* gB[2] = { Whi + (size_t)w * WSZ + (size_t)tn * EMB,
                                   Wlo + (size_t)w * WSZ + (size_t)tn * EMB };

    auto stage = [&](int buf, int kc) {
        const uint32_t base = sb + buf * STAGE_B;
        const int gcol = kc * 32 + (c16 >> 1);
#pragma unroll
        for (int t = 0; t < 2; t++) {
            int row = r0 + t * 64;
            uint32_t so = row * ROWB + c16;
            cp_async16(base + ST_AH + so, gA[0] + (size_t)row * EMB + gcol);
            cp_async16(base + ST_AL + so, gA[1] + (size_t)row * EMB + gcol);
            cp_async16(base + ST_BH + so, gB[0] + (size_t)row * EMB + gcol);
            cp_async16(base + ST_BL + so, gB[1] + (size_t)row * EMB + gcol);
        }
        CP_COMMIT();
    };

    GEMM_MAINLOOP()

    // epilogue: split bf16, scatter to [B,H,S,D]
    const int g   = lid >> 2;
    const int tig = lid & 3;
#pragma unroll
    for (int ni = 0; ni < 4; ni++) {
        const int n = tn + wn * 32 + ni * 8 + tig * 2;
        const float b0 = bias[n], b1 = bias[n + 1];
        const int hh = n >> 6, dd = n & 63;
#pragma unroll
        for (int mi = 0; mi < 4; mi++) {
#pragma unroll
            for (int half = 0; half < 2; half++) {
                int m = tm + wm * 64 + mi * 16 + g + half * 8;
                float vx = acc[mi][ni][half * 2 + 0] + b0;
                float vy = acc[mi][ni][half * 2 + 1] + b1;
                int bb = m >> 11, ss = m & 2047;
                size_t idx = (((size_t)(bb * NH + hh) * S_LEN) + ss) * HD + dd;
                __nv_bfloat16 hx = __float2bfloat16(vx);
                __nv_bfloat16 hy = __float2bfloat16(vy);
                __nv_bfloat16 lx = __float2bfloat16(vx - __bfloat162float(hx));
                __nv_bfloat16 ly = __float2bfloat16(vy - __bfloat162float(hy));
                *(__nv_bfloat162*)(Chi + idx) = __halves2bfloat162(hx, hy);
                *(__nv_bfloat162*)(Clo + idx) = __halves2bfloat162(lx, ly);
            }
        }
    }
}

// output projection GEMM: fp32 C row-major
__global__ void __launch_bounds__(256, 2)
gemm_out(const __nv_bfloat16* __restrict__ Ahi, const __nv_bfloat16* __restrict__ Alo,
         const __nv_bfloat16* __restrict__ Bhi, const __nv_bfloat16* __restrict__ Blo,
         const float* __restrict__ bias, float* __restrict__ C)
{
    extern __shared__ char smem[];
    const uint32_t sb = smem_u32(smem);
    const int tid = threadIdx.x;
    const int wid = tid >> 5;
    const int lid = tid & 31;
    const int tm  = blockIdx.y * 128;
    const int tn  = blockIdx.x * 128;
    const int wm  = wid >> 2;
    const int wn  = wid & 3;

    const int r0 = tid >> 2;
    const int c16 = (tid & 3) * 16;
    const __nv_bfloat16* gA[2] = { Ahi + (size_t)tm * EMB, Alo + (size_t)tm * EMB };
    const __nv_bfloat16* gB[2] = { Bhi + (size_t)tn * EMB, Blo + (size_t)tn * EMB };

    auto stage = [&](int buf, int kc) {
        const uint32_t base = sb + buf * STAGE_B;
        const int gcol = kc * 32 + (c16 >> 1);
#pragma unroll
        for (int t = 0; t < 2; t++) {
            int row = r0 + t * 64;
            uint32_t so = row * ROWB + c16;
            cp_async16(base + ST_AH + so, gA[0] + (size_t)row * EMB + gcol);
            cp_async16(base + ST_AL + so, gA[1] + (size_t)row * EMB + gcol);
            cp_async16(base + ST_BH + so, gB[0] + (size_t)row * EMB + gcol);
            cp_async16(base + ST_BL + so, gB[1] + (size_t)row * EMB + gcol);
        }
        CP_COMMIT();
    };

    GEMM_MAINLOOP()

    const int g   = lid >> 2;
    const int tig = lid & 3;
#pragma unroll
    for (int ni = 0; ni < 4; ni++) {
        const int n = tn + wn * 32 + ni * 8 + tig * 2;
        const float b0 = bias[n], b1 = bias[n + 1];
#pragma unroll
        for (int mi = 0; mi < 4; mi++) {
#pragma unroll
            for (int half = 0; half < 2; half++) {
                int m = tm + wm * 64 + mi * 16 + g + half * 8;
                float2 v;
                v.x = acc[mi][ni][half * 2 + 0] + b0;
                v.y = acc[mi][ni][half * 2 + 1] + b1;
                *(float2*)(C + (size_t)m * EMB + n) = v;
            }
        }
    }
}

// ---------------------------------------------------------------------------
// Flash attention: Q hi/lo persistent in smem, 2-stage KV, 2 CTAs/SM
// ---------------------------------------------------------------------------
#define FROWB 144
#define FQ_H  0                       // 128*144 = 18432
#define FQ_L  18432
#define F_KH  0
#define F_KL  9216
#define F_VH  18432
#define F_VL  27648
#define F_STAGE 36864
#define F_STG0 36864                  // KV stages start after Q region
#define FLASH_SMEM (F_STG0 + 2 * F_STAGE)   // 110592
#define NCHUNK (S_LEN / 64)           // 32

__global__ void __launch_bounds__(256, 2)
flash_mma(const __nv_bfloat16* __restrict__ Qhi, const __nv_bfloat16* __restrict__ Qlo,
          const __nv_bfloat16* __restrict__ Khi, const __nv_bfloat16* __restrict__ Klo,
          const __nv_bfloat16* __restrict__ Vhi, const __nv_bfloat16* __restrict__ Vlo,
          __nv_bfloat16* __restrict__ Ohi, __nv_bfloat16* __restrict__ Olo)
{
    extern __shared__ char smem[];
    const uint32_t sb = smem_u32(smem);
    const int tid = threadIdx.x;
    const int wid = tid >> 5;
    const int lid = tid & 31;
    const int bh  = blockIdx.y;
    const int b   = bh >> 4;
    const int h   = bh & 15;
    const int q0  = blockIdx.x * 128;

    const __nv_bfloat16* Qh_g = Qhi + ((size_t)bh * S_LEN + q0) * HD;
    const __nv_bfloat16* Ql_g = Qlo + ((size_t)bh * S_LEN + q0) * HD;
    const __nv_bfloat16* Kh_g = Khi + (size_t)bh * S_LEN * HD;
    const __nv_bfloat16* Kl_g = Klo + (size_t)bh * S_LEN * HD;
    const __nv_bfloat16* Vh_g = Vhi + (size_t)bh * S_LEN * HD;
    const __nv_bfloat16* Vl_g = Vlo + (size_t)bh * S_LEN * HD;

    // ---- KV staging ----
    const int s_row = tid >> 2;
    auto stage = [&](int c) {
        const uint32_t base = sb + F_STG0 + (c & 1) * F_STAGE;
        const size_t gbase = (size_t)(c * 64 + s_row) * HD;
#pragma unroll
        for (int t = 0; t < 2; t++) {
            int seg = (tid & 3) + t * 4;
            uint32_t so = s_row * FROWB + seg * 16;
            const size_t go = gbase + seg * 8;
            cp_async16(base + F_KH + so, Kh_g + go);
            cp_async16(base + F_KL + so, Kl_g + go);
            cp_async16(base + F_VH + so, Vh_g + go);
            cp_async16(base + F_VL + so, Vl_g + go);
        }
        CP_COMMIT();
    };

    stage(0);   // prefetch first KV chunk, overlaps Q staging below

    // ---- stage Q (128 x 64) hi/lo into persistent smem region ----
    {
        int row = tid >> 1;
#pragma unroll
        for (int t = 0; t < 4; t++) {
            int seg = (tid & 1) * 4 + t;
            *(uint4*)(smem + FQ_H + row * FROWB + seg * 16) =
                *(const uint4*)(Qh_g + (size_t)row * HD + seg * 8);
            *(uint4*)(smem + FQ_L + row * FROWB + seg * 16) =
                *(const uint4*)(Ql_g + (size_t)row * HD + seg * 8);
        }
    }
    __syncthreads();

    float o[8][4];
#pragma unroll
    for (int ni = 0; ni < 8; ni++)
#pragma unroll
        for (int j = 0; j < 4; j++) o[ni][j] = 0.0f;
    float m0 = -1e30f, m1 = -1e30f, l0 = 0.0f, l1 = 0.0f;

    const int a_row = wid * 16 + (lid & 15);
    const int a_kh  = (lid >> 4) * 16;
    const int b_row = lid & 7;
    const int b_kh  = ((lid >> 3) & 1) * 16;
    const int v_row = lid & 15;

#pragma unroll 1
    for (int c = 0; c < NCHUNK; c++) {
        CP_WAIT(0);
        __syncthreads();
        if (c + 1 < NCHUNK) stage(c + 1);
        const uint32_t bufb = sb + F_STG0 + (c & 1) * F_STAGE;

        // ---- scores: S = Qh·Kh + Qh·Kl + Ql·Kh (Q frags reloaded per ks) ----
        float sc[8][4];
#pragma unroll
        for (int ni = 0; ni < 8; ni++)
#pragma unroll
            for (int j = 0; j < 4; j++) sc[ni][j] = 0.0f;

#pragma unroll
        for (int ks = 0; ks < 4; ks++) {
            uint32_t qh4[4], ql4[4];
            uint32_t ra = a_row * FROWB + ks * 32 + a_kh;
            ldm_x4(qh4, sb + FQ_H + ra);
            ldm_x4(ql4, sb + FQ_L + ra);
            const uint32_t kso = ks * 32 + b_kh;
#pragma unroll
            for (int ni = 0; ni < 8; ni++) {
                uint32_t kh[2], kl[2];
                uint32_t rb = (ni * 8 + b_row) * FROWB + kso;
                ldm_x2(kh, bufb + F_KH + rb);
                ldm_x2(kl, bufb + F_KL + rb);
                mma_bf16(sc[ni], qh4, kh);
                mma_bf16(sc[ni], qh4, kl);
                mma_bf16(sc[ni], ql4, kh);
            }
        }

        // ---- online softmax ----
        float mx0 = -1e30f, mx1 = -1e30f;
#pragma unroll
        for (int ni = 0; ni < 8; ni++) {
            mx0 = fmaxf(mx0, fmaxf(sc[ni][0], sc[ni][1]));
            mx1 = fmaxf(mx1, fmaxf(sc[ni][2], sc[ni][3]));
        }
        mx0 *= 0.125f; mx1 *= 0.125f;
        mx0 = fmaxf(mx0, __shfl_xor_sync(~0u, mx0, 1));
        mx0 = fmaxf(mx0, __shfl_xor_sync(~0u, mx0, 2));
        mx1 = fmaxf(mx1, __shfl_xor_sync(~0u, mx1, 1));
        mx1 = fmaxf(mx1, __shfl_xor_sync(~0u, mx1, 2));
        float mn0 = fmaxf(m0, mx0), mn1 = fmaxf(m1, mx1);
        float corr0 = __expf(m0 - mn0), corr1 = __expf(m1 - mn1);
        m0 = mn0; m1 = mn1;

        float s0 = 0.0f, s1 = 0.0f;
#pragma unroll
        for (int ni = 0; ni < 8; ni++) {
            sc[ni][0] = __expf(fmaf(sc[ni][0], 0.125f, -mn0));
            sc[ni][1] = __expf(fmaf(sc[ni][1], 0.125f, -mn0));
            sc[ni][2] = __expf(fmaf(sc[ni][2], 0.125f, -mn1));
            sc[ni][3] = __expf(fmaf(sc[ni][3], 0.125f, -mn1));
            s0 += sc[ni][0] + sc[ni][1];
            s1 += sc[ni][2] + sc[ni][3];
        }
        s0 += __shfl_xor_sync(~0u, s0, 1);
        s0 += __shfl_xor_sync(~0u, s0, 2);
        s1 += __shfl_xor_sync(~0u, s1, 1);
        s1 += __shfl_xor_sync(~0u, s1, 2);
        l0 = l0 * corr0 + s0;
        l1 = l1 * corr1 + s1;

#pragma unroll
        for (int ni = 0; ni < 8; ni++) {
            o[ni][0] *= corr0; o[ni][1] *= corr0;
            o[ni][2] *= corr1; o[ni][3] *= corr1;
        }

        // ---- pack P into A-fragments (hi/lo) ----
        uint32_t ph[4][4], pl[4][4];
#pragma unroll
        for (int kk = 0; kk < 4; kk++) {
            float p00 = sc[2 * kk][0],     p01 = sc[2 * kk][1];
            float p02 = sc[2 * kk][2],     p03 = sc[2 * kk][3];
            float p10 = sc[2 * kk + 1][0], p11 = sc[2 * kk + 1][1];
            float p12 = sc[2 * kk + 1][2], p13 = sc[2 * kk + 1][3];
            __nv_bfloat16 h00 = __float2bfloat16(p00), h01 = __float2bfloat16(p01);
            __nv_bfloat16 h02 = __float2bfloat16(p02), h03 = __float2bfloat16(p03);
            __nv_bfloat16 h10 = __float2bfloat16(p10), h11 = __float2bfloat16(p11);
            __nv_bfloat16 h12 = __float2bfloat16(p12), h13 = __float2bfloat16(p13);
            ph[kk][0] = pack_bf16x2(p00, p01);
            ph[kk][1] = pack_bf16x2(p02, p03);
            ph[kk][2] = pack_bf16x2(p10, p11);
            ph[kk][3] = pack_bf16x2(p12, p13);
            pl[kk][0] = pack_bf16x2(p00 - __bfloat162float(h00), p01 - __bfloat162float(h01));
            pl[kk][1] = pack_bf16x2(p02 - __bfloat162float(h02), p03 - __bfloat162float(h03));
            pl[kk][2] = pack_bf16x2(p10 - __bfloat162float(h10), p11 - __bfloat162float(h11));
            pl[kk][3] = pack_bf16x2(p12 - __bfloat162float(h12), p13 - __bfloat162float(h13));
        }

        // ---- O += Ph·Vh + Ph·Vl + Pl·Vh ----
#pragma unroll
        for (int ks = 0; ks < 4; ks++) {
#pragma unroll
            for (int ni = 0; ni < 8; ni++) {
                uint32_t vh[2], vl[2];
                uint32_t rv = (ks * 16 + v_row) * FROWB + ni * 16;
                ldm_x2_t(vh, bufb + F_VH + rv);
                ldm_x2_t(vl, bufb + F_VL + rv);
                mma_bf16(o[ni], ph[ks], vh);
                mma_bf16(o[ni], ph[ks], vl);
                mma_bf16(o[ni], pl[ks], vh);
            }
        }
    }

    // ---- epilogue ----
    const int g   = lid >> 2;
    const int tig = lid & 3;
    const float inv0 = 1.0f / l0, inv1 = 1.0f / l1;
#pragma unroll
    for (int half = 0; half < 2; half++) {
        int s = q0 + wid * 16 + g + half * 8;
        float inv = half ? inv1 : inv0;
        size_t rowbase = ((size_t)(b * S_LEN + s)) * EMB + h * HD;
#pragma unroll
        for (int ni = 0; ni < 8; ni++) {
            float vx = o[ni][half * 2 + 0] * inv;
            float vy = o[ni][half * 2 + 1] * inv;
            __nv_bfloat16 hx = __float2bfloat16(vx);
            __nv_bfloat16 hy = __float2bfloat16(vy);
            __nv_bfloat16 lx = __float2bfloat16(vx - __bfloat162float(hx));
            __nv_bfloat16 ly = __float2bfloat16(vy - __bfloat162float(hy));
            size_t idx = rowbase + ni * 8 + tig * 2;
            *(__nv_bfloat162*)(Ohi + idx) = __halves2bfloat162(hx, hy);
            *(__nv_bfloat162*)(Olo + idx) = __halves2bfloat162(lx, ly);
        }
    }
}

// ---------------------------------------------------------------------------
// Launch
// ---------------------------------------------------------------------------
extern "C" void kernel_launch(void* const* d_in, const int* in_sizes, int n_in,
                              void* d_out, int out_size)
{
    const float* x  = (const float*)d_in[0];
    const float* Wq = (const float*)d_in[1];
    const float* bq = (const float*)d_in[2];
    const float* Wk = (const float*)d_in[3];
    const float* bk = (const float*)d_in[4];
    const float* Wv = (const float*)d_in[5];
    const float* bv = (const float*)d_in[6];
    const float* Wo = (const float*)d_in[7];
    const float* bo = (const float*)d_in[8];
    float* out = (float*)d_out;

    __nv_bfloat16 *xhi, *xlo, *whi, *wlo, *ahi, *alo;
    __nv_bfloat16 *qhi, *qlo, *khi, *klo, *vhi, *vlo;
    cudaGetSymbolAddress((void**)&xhi, g_xhi);
    cudaGetSymbolAddress((void**)&xlo, g_xlo);
    cudaGetSymbolAddress((void**)&whi, g_whi);
    cudaGetSymbolAddress((void**)&wlo, g_wlo);
    cudaGetSymbolAddress((void**)&ahi, g_ahi);
    cudaGetSymbolAddress((void**)&alo, g_alo);
    cudaGetSymbolAddress((void**)&qhi, g_qhi);
    cudaGetSymbolAddress((void**)&qlo, g_qlo);
    cudaGetSymbolAddress((void**)&khi, g_khi);
    cudaGetSymbolAddress((void**)&klo, g_klo);
    cudaGetSymbolAddress((void**)&vhi, g_vhi);
    cudaGetSymbolAddress((void**)&vlo, g_vlo);

    cudaFuncSetAttribute(gemm_qkv, cudaFuncAttributeMaxDynamicSharedMemorySize, GEMM_SMEM);
    cudaFuncSetAttribute(gemm_out, cudaFuncAttributeMaxDynamicSharedMemorySize, GEMM_SMEM);
    cudaFuncSetAttribute(flash_mma, cudaFuncAttributeMaxDynamicSharedMemorySize, FLASH_SMEM);

    convert_all<<<(N4ALL + 255) / 256, 256>>>((const float4*)x,
        (const float4*)Wq, (const float4*)Wk, (const float4*)Wv, (const float4*)Wo,
        xhi, xlo, whi, wlo);

    dim3 gq(24, M_TOT / 128);          // fused QKV
    gemm_qkv<<<gq, 256, GEMM_SMEM>>>(xhi, xlo, whi, wlo, bq, bk, bv,
                                     qhi, qlo, khi, klo, vhi, vlo);

    dim3 ga(S_LEN / 128, BH);          // (16, 64)
    flash_mma<<<ga, 256, FLASH_SMEM>>>(qhi, qlo, khi, klo, vhi, vlo, ahi, alo);

    dim3 gg(EMB / 128, M_TOT / 128);   // (8, 64)
    gemm_out<<<gg, 256, GEMM_SMEM>>>(ahi, alo, whi + 3 * WSZ, wlo + 3 * WSZ, bo, out);
}